// round 5
// baseline (speedup 1.0000x reference)
#include <cuda_runtime.h>
#include <cstdint>

#define NTOK 65536
#define OUT_ANG 0
#define OUT_UN  (NTOK*14)
#define OUT_POS (2*NTOK*14)
#define OUT_ATG (2*NTOK*14 + NTOK*42)

// smem byte offsets (mlp kernel)
#define SM_W    0            // 131072 B  (weights, hi/lo interleaved, swizzled)
#define SM_X    131072       // 65536 B   (activations, permuted+swizzled)
#define SM_BIAS 196608       // 2560 B    (5 x 128 floats)
#define SM_UNB  199168       // 7168 B    (unnorm 128x14)
#define SM_TOT  206336
// aliases into SM_W after last GEMM:
#define FS_STRIDE 129        // natural-layout final activations (128 x 129 floats)
#define SM_OWS  66560        // head weights (1792 floats) inside W region

__device__ float wbuf[6 * 32768];   // pre-split weights, smem image per layer

__device__ __forceinline__ uint32_t f2tf32(float f) {
    uint32_t r; asm("cvt.rna.tf32.f32 %0,%1;" : "=r"(r) : "f"(f)); return r;
}
__device__ __forceinline__ void mma_tf32(float c[4], uint32_t a0, uint32_t a1,
                                         uint32_t a2, uint32_t a3,
                                         uint32_t b0, uint32_t b1) {
    asm("mma.sync.aligned.m16n8k8.row.col.f32.tf32.tf32.f32 "
        "{%0,%1,%2,%3}, {%4,%5,%6,%7}, {%8,%9}, {%0,%1,%2,%3};"
        : "+f"(c[0]), "+f"(c[1]), "+f"(c[2]), "+f"(c[3])
        : "r"(a0), "r"(a1), "r"(a2), "r"(a3), "r"(b0), "r"(b1));
}

// ---------------------------------------------------------------------------
// prep kernel: split W (fp32) -> (hi,lo) tf32, write smem-image layout.
// Element (k,n) of layer L: group base = n*256 + (k>>3)*16 + (k&3)*4, XOR (n&1)<<4;
// slot = (k>>2)&1 for hi, +2 for lo.
// ---------------------------------------------------------------------------
__global__ void prep_kernel(const float* __restrict__ Wa, const float* __restrict__ Wi,
                            const float* __restrict__ w1, const float* __restrict__ w2) {
    int layer = blockIdx.x >> 6;
    int e = ((blockIdx.x & 63) << 8) + threadIdx.x;   // 0..16383
    const float* src;
    switch (layer) {
        case 0: src = Wa; break;
        case 1: src = Wi; break;
        case 2: src = w1; break;
        case 3: src = w2; break;
        case 4: src = w1 + 16384; break;
        default: src = w2 + 16384; break;
    }
    float w = src[e];
    int k = e >> 7, n = e & 127;
    uint32_t hi = f2tf32(w);
    uint32_t lo = f2tf32(w - __uint_as_float(hi));
    int grp = (((k >> 3) * 16 + (k & 3) * 4) ^ ((n & 1) << 4));
    int slot = ((k >> 2) & 1);
    float* dst = wbuf + layer * 32768 + n * 256 + grp;
    dst[slot]     = __uint_as_float(hi);
    dst[slot + 2] = __uint_as_float(lo);
}

// ---------------------------------------------------------------------------
// MLP kernel: 128 tokens/CTA, 256 threads, mma.sync tf32 3-pass.
// ---------------------------------------------------------------------------

// write value into permuted+swizzled X smem: pos(c)=2*(c&3)+((c>>2)&1)
__device__ __forceinline__ void writeX(float* Xs, int row, int col, float v) {
    int c = col & 7;
    int jx = (((col >> 3) << 3) + (((c & 3) << 1) | ((c >> 2) & 1))) ^ ((row & 3) << 3);
    Xs[row * 128 + jx] = v;
}

__device__ __forceinline__ void stageX_relu(float* Xs, const float* __restrict__ g,
                                            int tokBase, int tid) {
    const float4* src = (const float4*)g;
#pragma unroll
    for (int i = 0; i < 16; i++) {
        int idx4 = tid + i * 256;
        int row = idx4 >> 5;
        int c4 = (idx4 & 31) * 4;
        float4 v = src[(size_t)(tokBase + row) * 32 + (idx4 & 31)];
        writeX(Xs, row, c4 + 0, fmaxf(v.x, 0.f));
        writeX(Xs, row, c4 + 1, fmaxf(v.y, 0.f));
        writeX(Xs, row, c4 + 2, fmaxf(v.z, 0.f));
        writeX(Xs, row, c4 + 3, fmaxf(v.w, 0.f));
    }
}

__device__ __forceinline__ void copyW(float* Wsm, int layer, int tid) {
    const float4* src = (const float4*)(wbuf + layer * 32768);
    float4* dst = (float4*)Wsm;
#pragma unroll
    for (int i = 0; i < 32; i++) dst[tid + i * 256] = src[tid + i * 256];
}

// one 128x128x128 GEMM: acc += X @ W (3-pass tf32 emulation)
__device__ __forceinline__ void gemm(const float* __restrict__ Wsm,
                                     const float* __restrict__ Xs,
                                     float acc[2][8][4], int wm, int wn, int lane) {
    const int lq = lane & 3, lr = lane >> 2;
#pragma unroll 1
    for (int kk = 0; kk < 16; kk++) {
        uint32_t ahi[2][4], alo[2][4];
        int jx = (kk * 8 + lq * 2) ^ ((lr & 3) << 3);   // FIX: (lr&3), matches writeX
#pragma unroll
        for (int mt = 0; mt < 2; mt++) {
            int r0 = wm * 32 + mt * 16 + lr;
            float2 x0 = *(const float2*)(Xs + r0 * 128 + jx);
            float2 x1 = *(const float2*)(Xs + (r0 + 8) * 128 + jx);
            uint32_t h;
            h = f2tf32(x0.x); ahi[mt][0] = h; alo[mt][0] = f2tf32(x0.x - __uint_as_float(h));
            h = f2tf32(x1.x); ahi[mt][1] = h; alo[mt][1] = f2tf32(x1.x - __uint_as_float(h));
            h = f2tf32(x0.y); ahi[mt][2] = h; alo[mt][2] = f2tf32(x0.y - __uint_as_float(h));
            h = f2tf32(x1.y); ahi[mt][3] = h; alo[mt][3] = f2tf32(x1.y - __uint_as_float(h));
        }
        int jb = (kk * 16 + lq * 4) ^ ((lr & 1) << 4);
#pragma unroll
        for (int nt = 0; nt < 8; nt++) {
            int n = wn * 64 + nt * 8 + lr;
            float4 bw = *(const float4*)(Wsm + n * 256 + jb);
            uint32_t b0h = __float_as_uint(bw.x), b1h = __float_as_uint(bw.y);
            uint32_t b0l = __float_as_uint(bw.z), b1l = __float_as_uint(bw.w);
#pragma unroll
            for (int mt = 0; mt < 2; mt++) {
                mma_tf32(acc[mt][nt], ahi[mt][0], ahi[mt][1], ahi[mt][2], ahi[mt][3], b0h, b1h);
                mma_tf32(acc[mt][nt], alo[mt][0], alo[mt][1], alo[mt][2], alo[mt][3], b0h, b1h);
                mma_tf32(acc[mt][nt], ahi[mt][0], ahi[mt][1], ahi[mt][2], ahi[mt][3], b0l, b1l);
            }
        }
    }
}

__device__ __forceinline__ void zero_acc(float acc[2][8][4]) {
#pragma unroll
    for (int mt = 0; mt < 2; mt++)
#pragma unroll
        for (int nt = 0; nt < 8; nt++)
#pragma unroll
            for (int d = 0; d < 4; d++) acc[mt][nt][d] = 0.f;
}

__global__ void __launch_bounds__(256, 1) mlp_kernel(
    const float* __restrict__ act, const float* __restrict__ init_act,
    const float* __restrict__ ba, const float* __restrict__ bi,
    const float* __restrict__ b1, const float* __restrict__ b2,
    const float* __restrict__ ow, const float* __restrict__ ob,
    float* __restrict__ out)
{
    extern __shared__ __align__(16) char smem[];
    float* Wsm = (float*)(smem + SM_W);
    float* Xs  = (float*)(smem + SM_X);
    float* bias_s = (float*)(smem + SM_BIAS);
    float* Un  = (float*)(smem + SM_UNB);
    float* Fs  = (float*)(smem + SM_W);
    float* ows = (float*)(smem + SM_OWS);

    const int tid = threadIdx.x;
    const int lane = tid & 31;
    const int wid = tid >> 5;
    const int wm = wid >> 1, wn = wid & 1;
    const int lq = lane & 3, lr = lane >> 2;
    const int tokBase = blockIdx.x * 128;

    // bias staging: 0=ba+bi, 1=b1[0], 2=b2[0], 3=b1[1], 4=b2[1]
    for (int i = tid; i < 640; i += 256) {
        int slot = i >> 7, c = i & 127;
        float v;
        if (slot == 0)      v = ba[c] + bi[c];
        else if (slot == 1) v = b1[c];
        else if (slot == 2) v = b2[c];
        else if (slot == 3) v = b1[128 + c];
        else                v = b2[128 + c];
        bias_s[i] = v;
    }

    float acc[2][8][4], xres[2][8][4];

    // ---- layer 1a: relu(act) @ Wa ----
    stageX_relu(Xs, act, tokBase, tid);
    copyW(Wsm, 0, tid);
    __syncthreads();
    zero_acc(acc);
    gemm(Wsm, Xs, acc, wm, wn, lane);
    __syncthreads();

    // ---- layer 1b: += relu(init_act) @ Wi ----
    stageX_relu(Xs, init_act, tokBase, tid);
    copyW(Wsm, 1, tid);
    __syncthreads();
    gemm(Wsm, Xs, acc, wm, wn, lane);
    __syncthreads();

    // epilogue 1: xres = acc + bias0; X <- relu(xres)
#pragma unroll
    for (int mt = 0; mt < 2; mt++)
#pragma unroll
        for (int nt = 0; nt < 8; nt++) {
            int c0 = wn * 64 + nt * 8 + lq * 2;
            int r0 = wm * 32 + mt * 16 + lr;
            float bv0 = bias_s[c0], bv1 = bias_s[c0 + 1];
            xres[mt][nt][0] = acc[mt][nt][0] + bv0;
            xres[mt][nt][1] = acc[mt][nt][1] + bv1;
            xres[mt][nt][2] = acc[mt][nt][2] + bv0;
            xres[mt][nt][3] = acc[mt][nt][3] + bv1;
            writeX(Xs, r0, c0, fmaxf(xres[mt][nt][0], 0.f));
            writeX(Xs, r0, c0 + 1, fmaxf(xres[mt][nt][1], 0.f));
            writeX(Xs, r0 + 8, c0, fmaxf(xres[mt][nt][2], 0.f));
            writeX(Xs, r0 + 8, c0 + 1, fmaxf(xres[mt][nt][3], 0.f));
        }

    // ---- resnet blocks ----
#pragma unroll 1
    for (int blk = 0; blk < 2; blk++) {
        // w1: h = relu(relu(x) @ w1 + b1)
        copyW(Wsm, 2 + blk * 2, tid);
        __syncthreads();
        zero_acc(acc);
        gemm(Wsm, Xs, acc, wm, wn, lane);
        __syncthreads();
        const float* bb1 = bias_s + 128 * (1 + blk * 2);
#pragma unroll
        for (int mt = 0; mt < 2; mt++)
#pragma unroll
            for (int nt = 0; nt < 8; nt++) {
                int c0 = wn * 64 + nt * 8 + lq * 2;
                int r0 = wm * 32 + mt * 16 + lr;
                float bv0 = bb1[c0], bv1 = bb1[c0 + 1];
                writeX(Xs, r0, c0, fmaxf(acc[mt][nt][0] + bv0, 0.f));
                writeX(Xs, r0, c0 + 1, fmaxf(acc[mt][nt][1] + bv1, 0.f));
                writeX(Xs, r0 + 8, c0, fmaxf(acc[mt][nt][2] + bv0, 0.f));
                writeX(Xs, r0 + 8, c0 + 1, fmaxf(acc[mt][nt][3] + bv1, 0.f));
            }
        __syncthreads();
        // w2: x += h @ w2 + b2
        copyW(Wsm, 3 + blk * 2, tid);
        __syncthreads();
        zero_acc(acc);
        gemm(Wsm, Xs, acc, wm, wn, lane);
        __syncthreads();
        const float* bb2 = bias_s + 128 * (2 + blk * 2);
        bool last = (blk == 1);
#pragma unroll
        for (int mt = 0; mt < 2; mt++)
#pragma unroll
            for (int nt = 0; nt < 8; nt++) {
                int c0 = wn * 64 + nt * 8 + lq * 2;
                int r0 = wm * 32 + mt * 16 + lr;
                float bv0 = bb2[c0], bv1 = bb2[c0 + 1];
                xres[mt][nt][0] += acc[mt][nt][0] + bv0;
                xres[mt][nt][1] += acc[mt][nt][1] + bv1;
                xres[mt][nt][2] += acc[mt][nt][2] + bv0;
                xres[mt][nt][3] += acc[mt][nt][3] + bv1;
                if (!last) {
                    writeX(Xs, r0, c0, fmaxf(xres[mt][nt][0], 0.f));
                    writeX(Xs, r0, c0 + 1, fmaxf(xres[mt][nt][1], 0.f));
                    writeX(Xs, r0 + 8, c0, fmaxf(xres[mt][nt][2], 0.f));
                    writeX(Xs, r0 + 8, c0 + 1, fmaxf(xres[mt][nt][3], 0.f));
                } else {
                    Fs[r0 * FS_STRIDE + c0]           = fmaxf(xres[mt][nt][0], 0.f);
                    Fs[r0 * FS_STRIDE + c0 + 1]       = fmaxf(xres[mt][nt][1], 0.f);
                    Fs[(r0 + 8) * FS_STRIDE + c0]     = fmaxf(xres[mt][nt][2], 0.f);
                    Fs[(r0 + 8) * FS_STRIDE + c0 + 1] = fmaxf(xres[mt][nt][3], 0.f);
                }
            }
        if (last) break;
        __syncthreads();
    }
    // stage head weights into ows (inside dead W region; W no longer read)
    for (int i = tid; i < 1792; i += 256) ows[i] = ow[i];
    __syncthreads();

    // ---- head: unnorm = relu(x) @ ow + ob ----
    {
        int t = tid & 127, hh = tid >> 7;
        int ch0 = hh * 7;
        float a[7];
#pragma unroll
        for (int c = 0; c < 7; c++) a[c] = 0.f;
        const float* Xp = Fs + t * FS_STRIDE;
#pragma unroll 4
        for (int k = 0; k < 128; k++) {
            float xv = Xp[k];
            const float* wp = ows + k * 14 + ch0;
#pragma unroll
            for (int c = 0; c < 7; c++) a[c] += xv * wp[c];
        }
#pragma unroll
        for (int c = 0; c < 7; c++) Un[t * 14 + ch0 + c] = a[c] + ob[ch0 + c];
    }
    __syncthreads();

    // ---- normalize + write angles/unnorm ----
    for (int i = tid; i < 896; i += 256) {
        int t = i & 127, a = i >> 7;
        float sv = Un[t * 14 + 2 * a];
        float cv = Un[t * 14 + 2 * a + 1];
        float inv = rsqrtf(sv * sv + cv * cv + 1e-12f);
        int tok = tokBase + t;
        out[OUT_UN + tok * 14 + 2 * a]      = sv;
        out[OUT_UN + tok * 14 + 2 * a + 1]  = cv;
        out[OUT_ANG + tok * 14 + 2 * a]     = sv * inv;
        out[OUT_ANG + tok * 14 + 2 * a + 1] = cv * inv;
    }
}

// ---------------------------------------------------------------------------
// Kernel B: frames + atoms, tables in smem, 128 tokens/block
// ---------------------------------------------------------------------------

__device__ __forceinline__ void compose34(float* __restrict__ o,
                                          const float* __restrict__ A,
                                          const float* __restrict__ Bm) {
#pragma unroll
    for (int r = 0; r < 3; r++) {
        float a0 = A[r*4+0], a1 = A[r*4+1], a2 = A[r*4+2], a3 = A[r*4+3];
#pragma unroll
        for (int c = 0; c < 3; c++)
            o[r*4+c] = a0 * Bm[c] + a1 * Bm[4+c] + a2 * Bm[8+c];
        o[r*4+3] = a0 * Bm[3] + a1 * Bm[7] + a2 * Bm[11] + a3;
    }
}

__global__ void __launch_bounds__(256) frames_kernel(
    const int* __restrict__ seq, const float* __restrict__ backb,
    const float* __restrict__ dframes, const int* __restrict__ gidx,
    const float* __restrict__ amask, const float* __restrict__ lit,
    float* __restrict__ out)
{
    __shared__ float sdf[21 * 8 * 16];     // 2688
    __shared__ float slit[21 * 14 * 3];    // 882
    __shared__ float sam[21 * 14];         // 294
    __shared__ int   sgi[21 * 14];         // 294
    __shared__ float saf[32][8][12];

    const int tid = threadIdx.x;
    for (int i = tid; i < 2688; i += 256) sdf[i] = dframes[i];
    for (int i = tid; i < 882; i += 256) slit[i] = lit[i];
    for (int i = tid; i < 294; i += 256) { sam[i] = amask[i]; sgi[i] = gidx[i]; }
    __syncthreads();

    const int g = tid & 7;
    const int tl = tid >> 3;             // 0..31

#pragma unroll 1
    for (int it = 0; it < 4; it++) {
        const int tok = blockIdx.x * 128 + it * 32 + tl;
        const int s = seq[tok];

        float sv, cv;
        if (g == 0) { sv = 0.f; cv = 1.f; }
        else {
            sv = out[OUT_ANG + tok * 14 + (g - 1) * 2];
            cv = out[OUT_ANG + tok * 14 + (g - 1) * 2 + 1];
        }

        const float* df = sdf + (s * 8 + g) * 16;
        float F[12];
#pragma unroll
        for (int r = 0; r < 3; r++) {
            float m0 = df[r*4+0], m1 = df[r*4+1], m2 = df[r*4+2], m3 = df[r*4+3];
            F[r*4+0] = m0;
            F[r*4+1] = cv * m1 + sv * m2;
            F[r*4+2] = cv * m2 - sv * m1;
            F[r*4+3] = m3;
        }
#pragma unroll
        for (int i = 0; i < 12; i++) saf[tl][g][i] = F[i];
        __syncthreads();

        if (g == 0) {
            float A[12], Bm[12], Cm[12];
#pragma unroll
            for (int i = 0; i < 12; i++) A[i] = saf[tl][4][i];
#pragma unroll
            for (int i = 0; i < 12; i++) Bm[i] = saf[tl][5][i];
            compose34(Cm, A, Bm);
#pragma unroll
            for (int i = 0; i < 12; i++) saf[tl][5][i] = Cm[i];
#pragma unroll
            for (int i = 0; i < 12; i++) Bm[i] = saf[tl][6][i];
            compose34(A, Cm, Bm);
#pragma unroll
            for (int i = 0; i < 12; i++) saf[tl][6][i] = A[i];
#pragma unroll
            for (int i = 0; i < 12; i++) Bm[i] = saf[tl][7][i];
            compose34(Cm, A, Bm);
#pragma unroll
            for (int i = 0; i < 12; i++) saf[tl][7][i] = Cm[i];
        }
        __syncthreads();

        {
            const float4* bk4 = (const float4*)(backb + (size_t)tok * 16);
            float Bk[12], L[12], G[12];
            float4 b0 = bk4[0], b1v = bk4[1], b2v = bk4[2];
            Bk[0]=b0.x; Bk[1]=b0.y; Bk[2]=b0.z;  Bk[3]=b0.w;
            Bk[4]=b1v.x; Bk[5]=b1v.y; Bk[6]=b1v.z; Bk[7]=b1v.w;
            Bk[8]=b2v.x; Bk[9]=b2v.y; Bk[10]=b2v.z; Bk[11]=b2v.w;
#pragma unroll
            for (int i = 0; i < 12; i++) L[i] = saf[tl][g][i];
            compose34(G, Bk, L);
            float* o = out + OUT_ATG + (size_t)tok * 128 + g * 16;
            ((float4*)o)[0] = make_float4(G[0], G[1], G[2], G[3]);
            ((float4*)o)[1] = make_float4(G[4], G[5], G[6], G[7]);
            ((float4*)o)[2] = make_float4(G[8], G[9], G[10], G[11]);
            ((float4*)o)[3] = make_float4(0.f, 0.f, 0.f, 1.f);
#pragma unroll
            for (int i = 0; i < 12; i++) saf[tl][g][i] = G[i];
        }
        __syncthreads();

        for (int i = tid; i < 448; i += 256) {
            int t2 = i / 14;
            int a = i % 14;
            int tok2 = blockIdx.x * 128 + it * 32 + t2;
            int s2 = seq[tok2];
            int idx = s2 * 14 + a;
            int gg = sgi[idx];
            float m = sam[idx];
            float lx = slit[idx*3+0], ly = slit[idx*3+1], lz = slit[idx*3+2];
            const float* Fp = saf[t2][gg];
            float px = (Fp[0]*lx + Fp[1]*ly + Fp[2]*lz  + Fp[3])  * m;
            float py = (Fp[4]*lx + Fp[5]*ly + Fp[6]*lz  + Fp[7])  * m;
            float pz = (Fp[8]*lx + Fp[9]*ly + Fp[10]*lz + Fp[11]) * m;
            float* po = out + OUT_POS + (size_t)tok2 * 42 + a * 3;
            po[0] = px; po[1] = py; po[2] = pz;
        }
        __syncthreads();
    }
}

// ---------------------------------------------------------------------------

extern "C" void kernel_launch(void* const* d_in, const int* in_sizes, int n_in,
                              void* d_out, int out_size) {
    const int*   seq      = (const int*)  d_in[0];
    const float* backb    = (const float*)d_in[1];
    const float* act      = (const float*)d_in[2];
    const float* init_act = (const float*)d_in[3];
    const float* Wa       = (const float*)d_in[4];
    const float* ba       = (const float*)d_in[5];
    const float* Wi       = (const float*)d_in[6];
    const float* bi       = (const float*)d_in[7];
    const float* w1       = (const float*)d_in[8];
    const float* b1       = (const float*)d_in[9];
    const float* w2       = (const float*)d_in[10];
    const float* b2       = (const float*)d_in[11];
    const float* ow       = (const float*)d_in[12];
    const float* ob       = (const float*)d_in[13];
    const float* dframes  = (const float*)d_in[14];
    const int*   gidx     = (const int*)  d_in[15];
    const float* amask    = (const float*)d_in[16];
    const float* lit      = (const float*)d_in[17];
    float* out = (float*)d_out;

    cudaFuncSetAttribute(mlp_kernel, cudaFuncAttributeMaxDynamicSharedMemorySize, SM_TOT);

    prep_kernel<<<384, 256>>>(Wa, Wi, w1, w2);
    mlp_kernel<<<NTOK / 128, 256, SM_TOT>>>(act, init_act, ba, bi, b1, b2, ow, ob, out);
    frames_kernel<<<NTOK / 128, 256>>>(seq, backb, dframes, gidx, amask, lit, out);
}

// round 7
// speedup vs baseline: 1.3173x; 1.3173x over previous
#include <cuda_runtime.h>
#include <cuda_bf16.h>
#include <cstdint>

#define NTOK 65536
#define OUT_ANG 0
#define OUT_UN  (NTOK*14)
#define OUT_POS (2*NTOK*14)
#define OUT_ATG (2*NTOK*14 + NTOK*42)

// smem byte offsets (mlp kernel)
#define SM_W    0            // 65536 B  uint2[128][64]  (weights hi/lo bf16x2, swizzled)
#define SM_X    65536        // 65536 B  uint2[128][64]  (activations hi/lo bf16x2, swizzled)
#define SM_BIAS 131072       // 2560 B   (5 x 128 floats)
#define SM_UNB  133632       // 7168 B   (unnorm 128x14)
#define SM_TOT  140800
// aliases (used only after the last GEMM):
#define FS_STRIDE 129        // final activations fp32, 128 x 129 floats @ byte 0 (66048 B)
#define SM_OWS  73728        // head weights (1792 floats), beyond FS end

// pre-split weights: 6 layers x 128 n x 64 pairs x {hi0,hi1,lo0,lo1} ushort
__device__ unsigned short wbuf16[6 * 128 * 64 * 4];

__device__ __forceinline__ void mma_bf16(float c[4], uint32_t a0, uint32_t a1,
                                         uint32_t a2, uint32_t a3,
                                         uint32_t b0, uint32_t b1) {
    asm("mma.sync.aligned.m16n8k16.row.col.f32.bf16.bf16.f32 "
        "{%0,%1,%2,%3}, {%4,%5,%6,%7}, {%8,%9}, {%0,%1,%2,%3};"
        : "+f"(c[0]), "+f"(c[1]), "+f"(c[2]), "+f"(c[3])
        : "r"(a0), "r"(a1), "r"(a2), "r"(a3), "r"(b0), "r"(b1));
}

// pack (x0 -> low, x1 -> high) into bf16x2 hi, and residual lo
__device__ __forceinline__ void packHiLo(float x0, float x1,
                                         uint32_t& hi2, uint32_t& lo2) {
    asm("cvt.rn.bf16x2.f32 %0,%1,%2;" : "=r"(hi2) : "f"(x1), "f"(x0));
    float h0 = __uint_as_float(hi2 << 16);
    float h1 = __uint_as_float(hi2 & 0xFFFF0000u);
    asm("cvt.rn.bf16x2.f32 %0,%1,%2;" : "=r"(lo2) : "f"(x1 - h1), "f"(x0 - h0));
}

// ---------------------------------------------------------------------------
// prep kernel: split W (fp32) -> (hi,lo) bf16, write smem-image layout.
// (k,n): pair p=k>>1, half=k&1, ps = p ^ ((n&7)<<3); ushort slot: hi at half, lo at 2+half.
// ---------------------------------------------------------------------------
__global__ void prep_kernel(const float* __restrict__ Wa, const float* __restrict__ Wi,
                            const float* __restrict__ w1, const float* __restrict__ w2) {
    int layer = blockIdx.x >> 6;
    int e = ((blockIdx.x & 63) << 8) + threadIdx.x;   // 0..16383
    const float* src;
    switch (layer) {
        case 0: src = Wa; break;
        case 1: src = Wi; break;
        case 2: src = w1; break;
        case 3: src = w2; break;
        case 4: src = w1 + 16384; break;
        default: src = w2 + 16384; break;
    }
    float w = src[e];
    int k = e >> 7, n = e & 127;
    __nv_bfloat16 hb = __float2bfloat16_rn(w);
    unsigned short hibits = __bfloat16_as_ushort(hb);
    float hf = __uint_as_float(((uint32_t)hibits) << 16);
    unsigned short lobits = __bfloat16_as_ushort(__float2bfloat16_rn(w - hf));
    int p = k >> 1, half = k & 1;
    int ps = p ^ ((n & 7) << 3);
    unsigned short* dst = wbuf16 + (((size_t)layer * 128 + n) * 64 + ps) * 4;
    dst[half]     = hibits;
    dst[2 + half] = lobits;
}

// ---------------------------------------------------------------------------
// MLP kernel: 128 tokens/CTA, 512 threads (16 warps, 4x4), bf16 m16n8k16 3-pass.
// ---------------------------------------------------------------------------

__device__ __forceinline__ void stageX_relu(uint2* __restrict__ Xu,
                                            const float* __restrict__ g,
                                            int tokBase, int tid) {
    const float4* src = (const float4*)g;
#pragma unroll
    for (int i = 0; i < 8; i++) {
        int idx4 = tid + i * 512;
        int row = idx4 >> 5;
        int q = idx4 & 31;                 // float4 index: cols 4q..4q+3, pairs 2q,2q+1
        float4 v = src[(size_t)(tokBase + row) * 32 + q];
        float r0 = fmaxf(v.x, 0.f), r1 = fmaxf(v.y, 0.f);
        float r2 = fmaxf(v.z, 0.f), r3 = fmaxf(v.w, 0.f);
        uint2 e0, e1;
        packHiLo(r0, r1, e0.x, e0.y);
        packHiLo(r2, r3, e1.x, e1.y);
        int sw = (row & 7) << 3;
        Xu[row * 64 + ((2 * q) ^ sw)]     = e0;
        Xu[row * 64 + ((2 * q + 1) ^ sw)] = e1;
    }
}

__device__ __forceinline__ void copyW(void* Wsm, int layer, int tid) {
    const float4* src = (const float4*)(wbuf16 + (size_t)layer * 32768);
    float4* dst = (float4*)Wsm;
#pragma unroll
    for (int i = 0; i < 8; i++) dst[tid + i * 512] = src[tid + i * 512];
}

// one 128x128x128 GEMM: acc += X @ W (3-pass bf16 emulation), no converts inside
__device__ __forceinline__ void gemm(const uint2* __restrict__ Wu,
                                     const uint2* __restrict__ Xu,
                                     float acc[2][4][4], int wm, int wn, int lane) {
    const int lq = lane & 3, lr = lane >> 2;
    const int sw = lr << 3;
#pragma unroll 1
    for (int kk = 0; kk < 8; kk++) {
        const int p0 = (kk * 8 + lq) ^ sw;
        const int p1 = (kk * 8 + 4 + lq) ^ sw;
        uint32_t ahi[2][4], alo[2][4];
#pragma unroll
        for (int mt = 0; mt < 2; mt++) {
            int r0 = (wm * 32 + mt * 16 + lr) * 64;
            uint2 v0 = Xu[r0 + p0];
            uint2 v1 = Xu[r0 + 512 + p0];       // row + 8
            uint2 v2 = Xu[r0 + p1];
            uint2 v3 = Xu[r0 + 512 + p1];
            ahi[mt][0] = v0.x; alo[mt][0] = v0.y;
            ahi[mt][1] = v1.x; alo[mt][1] = v1.y;
            ahi[mt][2] = v2.x; alo[mt][2] = v2.y;
            ahi[mt][3] = v3.x; alo[mt][3] = v3.y;
        }
#pragma unroll
        for (int nt = 0; nt < 4; nt++) {
            int n = (wn * 32 + nt * 8 + lr) * 64;   // (n&7)==lr -> same sw
            uint2 b0 = Wu[n + p0];
            uint2 b1 = Wu[n + p1];
#pragma unroll
            for (int mt = 0; mt < 2; mt++) {
                mma_bf16(acc[mt][nt], ahi[mt][0], ahi[mt][1], ahi[mt][2], ahi[mt][3], b0.x, b1.x);
                mma_bf16(acc[mt][nt], alo[mt][0], alo[mt][1], alo[mt][2], alo[mt][3], b0.x, b1.x);
                mma_bf16(acc[mt][nt], ahi[mt][0], ahi[mt][1], ahi[mt][2], ahi[mt][3], b0.y, b1.y);
            }
        }
    }
}

__device__ __forceinline__ void zero_acc(float acc[2][4][4]) {
#pragma unroll
    for (int mt = 0; mt < 2; mt++)
#pragma unroll
        for (int nt = 0; nt < 4; nt++)
#pragma unroll
            for (int d = 0; d < 4; d++) acc[mt][nt][d] = 0.f;
}

// write relu(x) hi/lo pairs into Xu for tile value quad (v0,v1 row r0; v2,v3 row r0+8)
__device__ __forceinline__ void writeX_tile(uint2* __restrict__ Xu, int r0, int p,
                                            float v0, float v1, float v2, float v3) {
    uint2 e;
    packHiLo(fmaxf(v0, 0.f), fmaxf(v1, 0.f), e.x, e.y);
    int lr7 = r0 & 7;
    Xu[r0 * 64 + (p ^ (lr7 << 3))] = e;
    packHiLo(fmaxf(v2, 0.f), fmaxf(v3, 0.f), e.x, e.y);
    Xu[(r0 + 8) * 64 + (p ^ (lr7 << 3))] = e;
}

__global__ void __launch_bounds__(512, 1) mlp_kernel(
    const float* __restrict__ act, const float* __restrict__ init_act,
    const float* __restrict__ ba, const float* __restrict__ bi,
    const float* __restrict__ b1, const float* __restrict__ b2,
    const float* __restrict__ ow, const float* __restrict__ ob,
    float* __restrict__ out)
{
    extern __shared__ __align__(16) char smem[];
    uint2* Wu = (uint2*)(smem + SM_W);
    uint2* Xu = (uint2*)(smem + SM_X);
    float* bias_s = (float*)(smem + SM_BIAS);
    float* Un  = (float*)(smem + SM_UNB);
    float* Fs  = (float*)smem;               // alias over W (+512B of X), post-GEMM only
    float* ows = (float*)(smem + SM_OWS);

    const int tid = threadIdx.x;
    const int lane = tid & 31;
    const int wid = tid >> 5;
    const int wm = wid >> 2, wn = wid & 3;
    const int lq = lane & 3, lr = lane >> 2;
    const int tokBase = blockIdx.x * 128;

    // bias staging: 0=ba+bi, 1=b1[0], 2=b2[0], 3=b1[1], 4=b2[1]
    for (int i = tid; i < 640; i += 512) {
        int slot = i >> 7, c = i & 127;
        float v;
        if (slot == 0)      v = ba[c] + bi[c];
        else if (slot == 1) v = b1[c];
        else if (slot == 2) v = b2[c];
        else if (slot == 3) v = b1[128 + c];
        else                v = b2[128 + c];
        bias_s[i] = v;
    }

    float acc[2][4][4], xres[2][4][4];

    // ---- layer 1a: relu(act) @ Wa ----
    stageX_relu(Xu, act, tokBase, tid);
    copyW(Wu, 0, tid);
    __syncthreads();
    zero_acc(acc);
    gemm(Wu, Xu, acc, wm, wn, lane);
    __syncthreads();

    // ---- layer 1b: += relu(init_act) @ Wi ----
    stageX_relu(Xu, init_act, tokBase, tid);
    copyW(Wu, 1, tid);
    __syncthreads();
    gemm(Wu, Xu, acc, wm, wn, lane);
    __syncthreads();

    // epilogue 1: xres = acc + bias0; X <- relu(xres)
#pragma unroll
    for (int mt = 0; mt < 2; mt++)
#pragma unroll
        for (int nt = 0; nt < 4; nt++) {
            int c0 = wn * 32 + nt * 8 + lq * 2;
            int r0 = wm * 32 + mt * 16 + lr;
            float bv0 = bias_s[c0], bv1 = bias_s[c0 + 1];
            xres[mt][nt][0] = acc[mt][nt][0] + bv0;
            xres[mt][nt][1] = acc[mt][nt][1] + bv1;
            xres[mt][nt][2] = acc[mt][nt][2] + bv0;
            xres[mt][nt][3] = acc[mt][nt][3] + bv1;
            writeX_tile(Xu, r0, c0 >> 1, xres[mt][nt][0], xres[mt][nt][1],
                        xres[mt][nt][2], xres[mt][nt][3]);
        }

    // ---- resnet blocks ----
#pragma unroll 1
    for (int blk = 0; blk < 2; blk++) {
        // w1: h = relu(relu(x) @ w1 + b1)
        copyW(Wu, 2 + blk * 2, tid);
        __syncthreads();
        zero_acc(acc);
        gemm(Wu, Xu, acc, wm, wn, lane);
        __syncthreads();
        const float* bb1 = bias_s + 128 * (1 + blk * 2);
#pragma unroll
        for (int mt = 0; mt < 2; mt++)
#pragma unroll
            for (int nt = 0; nt < 4; nt++) {
                int c0 = wn * 32 + nt * 8 + lq * 2;
                int r0 = wm * 32 + mt * 16 + lr;
                float bv0 = bb1[c0], bv1 = bb1[c0 + 1];
                writeX_tile(Xu, r0, c0 >> 1, acc[mt][nt][0] + bv0, acc[mt][nt][1] + bv1,
                            acc[mt][nt][2] + bv0, acc[mt][nt][3] + bv1);
            }
        __syncthreads();
        // w2: x += h @ w2 + b2
        copyW(Wu, 3 + blk * 2, tid);
        __syncthreads();
        zero_acc(acc);
        gemm(Wu, Xu, acc, wm, wn, lane);
        __syncthreads();
        const float* bb2 = bias_s + 128 * (2 + blk * 2);
        bool last = (blk == 1);
#pragma unroll
        for (int mt = 0; mt < 2; mt++)
#pragma unroll
            for (int nt = 0; nt < 4; nt++) {
                int c0 = wn * 32 + nt * 8 + lq * 2;
                int r0 = wm * 32 + mt * 16 + lr;
                float bv0 = bb2[c0], bv1 = bb2[c0 + 1];
                xres[mt][nt][0] += acc[mt][nt][0] + bv0;
                xres[mt][nt][1] += acc[mt][nt][1] + bv1;
                xres[mt][nt][2] += acc[mt][nt][2] + bv0;
                xres[mt][nt][3] += acc[mt][nt][3] + bv1;
                if (!last) {
                    writeX_tile(Xu, r0, c0 >> 1, xres[mt][nt][0], xres[mt][nt][1],
                                xres[mt][nt][2], xres[mt][nt][3]);
                } else {
                    Fs[r0 * FS_STRIDE + c0]           = fmaxf(xres[mt][nt][0], 0.f);
                    Fs[r0 * FS_STRIDE + c0 + 1]       = fmaxf(xres[mt][nt][1], 0.f);
                    Fs[(r0 + 8) * FS_STRIDE + c0]     = fmaxf(xres[mt][nt][2], 0.f);
                    Fs[(r0 + 8) * FS_STRIDE + c0 + 1] = fmaxf(xres[mt][nt][3], 0.f);
                }
            }
        if (last) break;
        __syncthreads();
    }
    // stage head weights into ows (beyond Fs end; W/X dead)
    for (int i = tid; i < 1792; i += 512) ows[i] = ow[i];
    __syncthreads();

    // ---- head: unnorm = relu(x) @ ow + ob ----
    {
        int t = tid & 127, hh = tid >> 7;    // hh 0..3
        int ch0 = hh * 4;
        int cnt = (hh == 3) ? 2 : 4;
        float a0 = 0.f, a1 = 0.f, a2 = 0.f, a3 = 0.f;
        const float* Xp = Fs + t * FS_STRIDE;
#pragma unroll 4
        for (int k = 0; k < 128; k++) {
            float xv = Xp[k];
            const float* wp = ows + k * 14 + ch0;
            a0 += xv * wp[0];
            a1 += xv * wp[1];
            if (hh != 3) { a2 += xv * wp[2]; a3 += xv * wp[3]; }
        }
        Un[t * 14 + ch0 + 0] = a0 + ob[ch0 + 0];
        Un[t * 14 + ch0 + 1] = a1 + ob[ch0 + 1];
        if (cnt == 4) {
            Un[t * 14 + ch0 + 2] = a2 + ob[ch0 + 2];
            Un[t * 14 + ch0 + 3] = a3 + ob[ch0 + 3];
        }
    }
    __syncthreads();

    // ---- normalize + write angles/unnorm ----
    for (int i = tid; i < 896; i += 512) {
        int t = i & 127, a = i >> 7;
        float sv = Un[t * 14 + 2 * a];
        float cv = Un[t * 14 + 2 * a + 1];
        float inv = rsqrtf(sv * sv + cv * cv + 1e-12f);
        int tok = tokBase + t;
        out[OUT_UN + tok * 14 + 2 * a]      = sv;
        out[OUT_UN + tok * 14 + 2 * a + 1]  = cv;
        out[OUT_ANG + tok * 14 + 2 * a]     = sv * inv;
        out[OUT_ANG + tok * 14 + 2 * a + 1] = cv * inv;
    }
}

// ---------------------------------------------------------------------------
// Kernel B: frames + atoms, tables in smem, 128 tokens/block (unchanged)
// ---------------------------------------------------------------------------

__device__ __forceinline__ void compose34(float* __restrict__ o,
                                          const float* __restrict__ A,
                                          const float* __restrict__ Bm) {
#pragma unroll
    for (int r = 0; r < 3; r++) {
        float a0 = A[r*4+0], a1 = A[r*4+1], a2 = A[r*4+2], a3 = A[r*4+3];
#pragma unroll
        for (int c = 0; c < 3; c++)
            o[r*4+c] = a0 * Bm[c] + a1 * Bm[4+c] + a2 * Bm[8+c];
        o[r*4+3] = a0 * Bm[3] + a1 * Bm[7] + a2 * Bm[11] + a3;
    }
}

__global__ void __launch_bounds__(256) frames_kernel(
    const int* __restrict__ seq, const float* __restrict__ backb,
    const float* __restrict__ dframes, const int* __restrict__ gidx,
    const float* __restrict__ amask, const float* __restrict__ lit,
    float* __restrict__ out)
{
    __shared__ float sdf[21 * 8 * 16];
    __shared__ float slit[21 * 14 * 3];
    __shared__ float sam[21 * 14];
    __shared__ int   sgi[21 * 14];
    __shared__ float saf[32][8][12];

    const int tid = threadIdx.x;
    for (int i = tid; i < 2688; i += 256) sdf[i] = dframes[i];
    for (int i = tid; i < 882; i += 256) slit[i] = lit[i];
    for (int i = tid; i < 294; i += 256) { sam[i] = amask[i]; sgi[i] = gidx[i]; }
    __syncthreads();

    const int g = tid & 7;
    const int tl = tid >> 3;

#pragma unroll 1
    for (int it = 0; it < 4; it++) {
        const int tok = blockIdx.x * 128 + it * 32 + tl;
        const int s = seq[tok];

        float sv, cv;
        if (g == 0) { sv = 0.f; cv = 1.f; }
        else {
            sv = out[OUT_ANG + tok * 14 + (g - 1) * 2];
            cv = out[OUT_ANG + tok * 14 + (g - 1) * 2 + 1];
        }

        const float* df = sdf + (s * 8 + g) * 16;
        float F[12];
#pragma unroll
        for (int r = 0; r < 3; r++) {
            float m0 = df[r*4+0], m1 = df[r*4+1], m2 = df[r*4+2], m3 = df[r*4+3];
            F[r*4+0] = m0;
            F[r*4+1] = cv * m1 + sv * m2;
            F[r*4+2] = cv * m2 - sv * m1;
            F[r*4+3] = m3;
        }
#pragma unroll
        for (int i = 0; i < 12; i++) saf[tl][g][i] = F[i];
        __syncthreads();

        if (g == 0) {
            float A[12], Bm[12], Cm[12];
#pragma unroll
            for (int i = 0; i < 12; i++) A[i] = saf[tl][4][i];
#pragma unroll
            for (int i = 0; i < 12; i++) Bm[i] = saf[tl][5][i];
            compose34(Cm, A, Bm);
#pragma unroll
            for (int i = 0; i < 12; i++) saf[tl][5][i] = Cm[i];
#pragma unroll
            for (int i = 0; i < 12; i++) Bm[i] = saf[tl][6][i];
            compose34(A, Cm, Bm);
#pragma unroll
            for (int i = 0; i < 12; i++) saf[tl][6][i] = A[i];
#pragma unroll
            for (int i = 0; i < 12; i++) Bm[i] = saf[tl][7][i];
            compose34(Cm, A, Bm);
#pragma unroll
            for (int i = 0; i < 12; i++) saf[tl][7][i] = Cm[i];
        }
        __syncthreads();

        {
            const float4* bk4 = (const float4*)(backb + (size_t)tok * 16);
            float Bk[12], L[12], G[12];
            float4 b0 = bk4[0], b1v = bk4[1], b2v = bk4[2];
            Bk[0]=b0.x; Bk[1]=b0.y; Bk[2]=b0.z;  Bk[3]=b0.w;
            Bk[4]=b1v.x; Bk[5]=b1v.y; Bk[6]=b1v.z; Bk[7]=b1v.w;
            Bk[8]=b2v.x; Bk[9]=b2v.y; Bk[10]=b2v.z; Bk[11]=b2v.w;
#pragma unroll
            for (int i = 0; i < 12; i++) L[i] = saf[tl][g][i];
            compose34(G, Bk, L);
            float* o = out + OUT_ATG + (size_t)tok * 128 + g * 16;
            ((float4*)o)[0] = make_float4(G[0], G[1], G[2], G[3]);
            ((float4*)o)[1] = make_float4(G[4], G[5], G[6], G[7]);
            ((float4*)o)[2] = make_float4(G[8], G[9], G[10], G[11]);
            ((float4*)o)[3] = make_float4(0.f, 0.f, 0.f, 1.f);
#pragma unroll
            for (int i = 0; i < 12; i++) saf[tl][g][i] = G[i];
        }
        __syncthreads();

        for (int i = tid; i < 448; i += 256) {
            int t2 = i / 14;
            int a = i % 14;
            int tok2 = blockIdx.x * 128 + it * 32 + t2;
            int s2 = seq[tok2];
            int idx = s2 * 14 + a;
            int gg = sgi[idx];
            float m = sam[idx];
            float lx = slit[idx*3+0], ly = slit[idx*3+1], lz = slit[idx*3+2];
            const float* Fp = saf[t2][gg];
            float px = (Fp[0]*lx + Fp[1]*ly + Fp[2]*lz  + Fp[3])  * m;
            float py = (Fp[4]*lx + Fp[5]*ly + Fp[6]*lz  + Fp[7])  * m;
            float pz = (Fp[8]*lx + Fp[9]*ly + Fp[10]*lz + Fp[11]) * m;
            float* po = out + OUT_POS + (size_t)tok2 * 42 + a * 3;
            po[0] = px; po[1] = py; po[2] = pz;
        }
        __syncthreads();
    }
}

// ---------------------------------------------------------------------------

extern "C" void kernel_launch(void* const* d_in, const int* in_sizes, int n_in,
                              void* d_out, int out_size) {
    const int*   seq      = (const int*)  d_in[0];
    const float* backb    = (const float*)d_in[1];
    const float* act      = (const float*)d_in[2];
    const float* init_act = (const float*)d_in[3];
    const float* Wa       = (const float*)d_in[4];
    const float* ba       = (const float*)d_in[5];
    const float* Wi       = (const float*)d_in[6];
    const float* bi       = (const float*)d_in[7];
    const float* w1       = (const float*)d_in[8];
    const float* b1       = (const float*)d_in[9];
    const float* w2       = (const float*)d_in[10];
    const float* b2       = (const float*)d_in[11];
    const float* ow       = (const float*)d_in[12];
    const float* ob       = (const float*)d_in[13];
    const float* dframes  = (const float*)d_in[14];
    const int*   gidx     = (const int*)  d_in[15];
    const float* amask    = (const float*)d_in[16];
    const float* lit      = (const float*)d_in[17];
    float* out = (float*)d_out;

    cudaFuncSetAttribute(mlp_kernel, cudaFuncAttributeMaxDynamicSharedMemorySize, SM_TOT);

    prep_kernel<<<384, 256>>>(Wa, Wi, w1, w2);
    mlp_kernel<<<NTOK / 128, 512, SM_TOT>>>(act, init_act, ba, bi, b1, b2, ow, ob, out);
    frames_kernel<<<NTOK / 128, 256>>>(seq, backb, dframes, gidx, amask, lit, out);
}

// round 8
// speedup vs baseline: 1.4155x; 1.0745x over previous
#include <cuda_runtime.h>
#include <cuda_bf16.h>
#include <cstdint>

#define NTOK 65536
#define OUT_ANG 0
#define OUT_UN  (NTOK*14)
#define OUT_POS (2*NTOK*14)
#define OUT_ATG (2*NTOK*14 + NTOK*42)

// row stride in uint2 (8B) units: 68 -> bank-pair = (4*row + p) mod 16, conflict-free
#define XSTRIDE 68
#define LAYER_U2 (128 * XSTRIDE)            // 8704 uint2 = 69632 B per tile

// smem byte offsets (mlp kernel)
#define SM_W    0                           // 69632 B
#define SM_X    69632                       // 69632 B
#define SM_BIAS 139264                      // 2560 B
#define SM_UNB  141824                      // 7168 B
#define SM_TOT  148992
// aliases (used only after the last GEMM):
#define FS_STRIDE 129                       // final activations fp32 @ byte 0 (66048 B)
#define SM_OWS  73728                       // head weights (1792 floats), beyond FS end

// pre-split weights: 6 layers, padded smem image (stride 68)
__device__ unsigned short wbuf16[6 * LAYER_U2 * 4];

__device__ __forceinline__ void mma_bf16(float c[4], uint32_t a0, uint32_t a1,
                                         uint32_t a2, uint32_t a3,
                                         uint32_t b0, uint32_t b1) {
    asm("mma.sync.aligned.m16n8k16.row.col.f32.bf16.bf16.f32 "
        "{%0,%1,%2,%3}, {%4,%5,%6,%7}, {%8,%9}, {%0,%1,%2,%3};"
        : "+f"(c[0]), "+f"(c[1]), "+f"(c[2]), "+f"(c[3])
        : "r"(a0), "r"(a1), "r"(a2), "r"(a3), "r"(b0), "r"(b1));
}

// pack (x0 -> low, x1 -> high) into bf16x2 hi, and residual lo
__device__ __forceinline__ void packHiLo(float x0, float x1,
                                         uint32_t& hi2, uint32_t& lo2) {
    asm("cvt.rn.bf16x2.f32 %0,%1,%2;" : "=r"(hi2) : "f"(x1), "f"(x0));
    float h0 = __uint_as_float(hi2 << 16);
    float h1 = __uint_as_float(hi2 & 0xFFFF0000u);
    asm("cvt.rn.bf16x2.f32 %0,%1,%2;" : "=r"(lo2) : "f"(x1 - h1), "f"(x0 - h0));
}

// ---------------------------------------------------------------------------
// prep kernel: split W (fp32) -> (hi,lo) bf16, write padded smem-image layout.
// (k,n): pair p=k>>1, half=k&1; dst = (n*68 + p); ushort slot: hi at half, lo at 2+half.
// ---------------------------------------------------------------------------
__global__ void prep_kernel(const float* __restrict__ Wa, const float* __restrict__ Wi,
                            const float* __restrict__ w1, const float* __restrict__ w2) {
    int layer = blockIdx.x >> 6;
    int e = ((blockIdx.x & 63) << 8) + threadIdx.x;   // 0..16383
    const float* src;
    switch (layer) {
        case 0: src = Wa; break;
        case 1: src = Wi; break;
        case 2: src = w1; break;
        case 3: src = w2; break;
        case 4: src = w1 + 16384; break;
        default: src = w2 + 16384; break;
    }
    float w = src[e];
    int k = e >> 7, n = e & 127;
    __nv_bfloat16 hb = __float2bfloat16_rn(w);
    unsigned short hibits = __bfloat16_as_ushort(hb);
    float hf = __uint_as_float(((uint32_t)hibits) << 16);
    unsigned short lobits = __bfloat16_as_ushort(__float2bfloat16_rn(w - hf));
    int p = k >> 1, half = k & 1;
    unsigned short* dst = wbuf16 + ((size_t)layer * LAYER_U2 + n * XSTRIDE + p) * 4;
    dst[half]     = hibits;
    dst[2 + half] = lobits;
}

// ---------------------------------------------------------------------------
// MLP kernel: 128 tokens/CTA, 512 threads (16 warps, 4x4), bf16 m16n8k16 3-pass.
// ---------------------------------------------------------------------------

__device__ __forceinline__ void stageX_relu(uint2* __restrict__ Xu,
                                            const float* __restrict__ g,
                                            int tokBase, int tid) {
    const float4* src = (const float4*)g;
#pragma unroll
    for (int i = 0; i < 8; i++) {
        int idx4 = tid + i * 512;
        int row = idx4 >> 5;
        int q = idx4 & 31;                 // float4 index: cols 4q..4q+3, pairs 2q,2q+1
        float4 v = src[(size_t)(tokBase + row) * 32 + q];
        float r0 = fmaxf(v.x, 0.f), r1 = fmaxf(v.y, 0.f);
        float r2 = fmaxf(v.z, 0.f), r3 = fmaxf(v.w, 0.f);
        uint2 e0, e1;
        packHiLo(r0, r1, e0.x, e0.y);
        packHiLo(r2, r3, e1.x, e1.y);
        Xu[row * XSTRIDE + 2 * q]     = e0;
        Xu[row * XSTRIDE + 2 * q + 1] = e1;
    }
}

__device__ __forceinline__ void copyW(void* Wsm, int layer, int tid) {
    const float4* src = (const float4*)(wbuf16 + (size_t)layer * LAYER_U2 * 4);
    float4* dst = (float4*)Wsm;
    // LAYER_U2*8 bytes / 16 = 4352 float4
#pragma unroll
    for (int i = 0; i < 8; i++) dst[tid + i * 512] = src[tid + i * 512];
    if (tid < 256) dst[tid + 4096] = src[tid + 4096];
}

// one 128x128x128 GEMM: acc += X @ W (3-pass bf16 emulation), conflict-free LDS
__device__ __forceinline__ void gemm(const uint2* __restrict__ Wu,
                                     const uint2* __restrict__ Xu,
                                     float acc[2][4][4], int wm, int wn, int lane) {
    const int lq = lane & 3, lr = lane >> 2;
#pragma unroll 1
    for (int kk = 0; kk < 8; kk++) {
        const int p0 = kk * 8 + lq;
        const int p1 = kk * 8 + 4 + lq;
        uint32_t ahi[2][4], alo[2][4];
#pragma unroll
        for (int mt = 0; mt < 2; mt++) {
            int r0 = (wm * 32 + mt * 16 + lr) * XSTRIDE;
            uint2 v0 = Xu[r0 + p0];
            uint2 v1 = Xu[r0 + 8 * XSTRIDE + p0];
            uint2 v2 = Xu[r0 + p1];
            uint2 v3 = Xu[r0 + 8 * XSTRIDE + p1];
            ahi[mt][0] = v0.x; alo[mt][0] = v0.y;
            ahi[mt][1] = v1.x; alo[mt][1] = v1.y;
            ahi[mt][2] = v2.x; alo[mt][2] = v2.y;
            ahi[mt][3] = v3.x; alo[mt][3] = v3.y;
        }
#pragma unroll
        for (int nt = 0; nt < 4; nt++) {
            int n = (wn * 32 + nt * 8 + lr) * XSTRIDE;
            uint2 b0 = Wu[n + p0];
            uint2 b1 = Wu[n + p1];
#pragma unroll
            for (int mt = 0; mt < 2; mt++) {
                mma_bf16(acc[mt][nt], ahi[mt][0], ahi[mt][1], ahi[mt][2], ahi[mt][3], b0.x, b1.x);
                mma_bf16(acc[mt][nt], alo[mt][0], alo[mt][1], alo[mt][2], alo[mt][3], b0.x, b1.x);
                mma_bf16(acc[mt][nt], ahi[mt][0], ahi[mt][1], ahi[mt][2], ahi[mt][3], b0.y, b1.y);
            }
        }
    }
}

__device__ __forceinline__ void zero_acc(float acc[2][4][4]) {
#pragma unroll
    for (int mt = 0; mt < 2; mt++)
#pragma unroll
        for (int nt = 0; nt < 4; nt++)
#pragma unroll
            for (int d = 0; d < 4; d++) acc[mt][nt][d] = 0.f;
}

// write relu(x) hi/lo pairs into Xu for tile value quad (v0,v1 row r0; v2,v3 row r0+8)
__device__ __forceinline__ void writeX_tile(uint2* __restrict__ Xu, int r0, int p,
                                            float v0, float v1, float v2, float v3) {
    uint2 e;
    packHiLo(fmaxf(v0, 0.f), fmaxf(v1, 0.f), e.x, e.y);
    Xu[r0 * XSTRIDE + p] = e;
    packHiLo(fmaxf(v2, 0.f), fmaxf(v3, 0.f), e.x, e.y);
    Xu[(r0 + 8) * XSTRIDE + p] = e;
}

__global__ void __launch_bounds__(512, 1) mlp_kernel(
    const float* __restrict__ act, const float* __restrict__ init_act,
    const float* __restrict__ ba, const float* __restrict__ bi,
    const float* __restrict__ b1, const float* __restrict__ b2,
    const float* __restrict__ ow, const float* __restrict__ ob,
    float* __restrict__ out)
{
    extern __shared__ __align__(16) char smem[];
    uint2* Wu = (uint2*)(smem + SM_W);
    uint2* Xu = (uint2*)(smem + SM_X);
    float* bias_s = (float*)(smem + SM_BIAS);
    float* Un  = (float*)(smem + SM_UNB);
    float* Fs  = (float*)smem;               // alias over W region, post-GEMM only
    float* ows = (float*)(smem + SM_OWS);

    const int tid = threadIdx.x;
    const int lane = tid & 31;
    const int wid = tid >> 5;
    const int wm = wid >> 2, wn = wid & 3;
    const int lq = lane & 3, lr = lane >> 2;
    const int tokBase = blockIdx.x * 128;

    // bias staging: 0=ba+bi, 1=b1[0], 2=b2[0], 3=b1[1], 4=b2[1]
    for (int i = tid; i < 640; i += 512) {
        int slot = i >> 7, c = i & 127;
        float v;
        if (slot == 0)      v = ba[c] + bi[c];
        else if (slot == 1) v = b1[c];
        else if (slot == 2) v = b2[c];
        else if (slot == 3) v = b1[128 + c];
        else                v = b2[128 + c];
        bias_s[i] = v;
    }

    float acc[2][4][4], xres[2][4][4];

    // ---- layer 1a: relu(act) @ Wa ----
    stageX_relu(Xu, act, tokBase, tid);
    copyW(Wu, 0, tid);
    __syncthreads();
    zero_acc(acc);
    gemm(Wu, Xu, acc, wm, wn, lane);
    __syncthreads();

    // ---- layer 1b: += relu(init_act) @ Wi ----
    stageX_relu(Xu, init_act, tokBase, tid);
    copyW(Wu, 1, tid);
    __syncthreads();
    gemm(Wu, Xu, acc, wm, wn, lane);
    __syncthreads();

    // epilogue 1: xres = acc + bias0; X <- relu(xres)
#pragma unroll
    for (int mt = 0; mt < 2; mt++)
#pragma unroll
        for (int nt = 0; nt < 4; nt++) {
            int c0 = wn * 32 + nt * 8 + lq * 2;
            int r0 = wm * 32 + mt * 16 + lr;
            float bv0 = bias_s[c0], bv1 = bias_s[c0 + 1];
            xres[mt][nt][0] = acc[mt][nt][0] + bv0;
            xres[mt][nt][1] = acc[mt][nt][1] + bv1;
            xres[mt][nt][2] = acc[mt][nt][2] + bv0;
            xres[mt][nt][3] = acc[mt][nt][3] + bv1;
            writeX_tile(Xu, r0, c0 >> 1, xres[mt][nt][0], xres[mt][nt][1],
                        xres[mt][nt][2], xres[mt][nt][3]);
        }

    // ---- resnet blocks ----
#pragma unroll 1
    for (int blk = 0; blk < 2; blk++) {
        // w1: h = relu(relu(x) @ w1 + b1)
        copyW(Wu, 2 + blk * 2, tid);
        __syncthreads();
        zero_acc(acc);
        gemm(Wu, Xu, acc, wm, wn, lane);
        __syncthreads();
        const float* bb1 = bias_s + 128 * (1 + blk * 2);
#pragma unroll
        for (int mt = 0; mt < 2; mt++)
#pragma unroll
            for (int nt = 0; nt < 4; nt++) {
                int c0 = wn * 32 + nt * 8 + lq * 2;
                int r0 = wm * 32 + mt * 16 + lr;
                float bv0 = bb1[c0], bv1 = bb1[c0 + 1];
                writeX_tile(Xu, r0, c0 >> 1, acc[mt][nt][0] + bv0, acc[mt][nt][1] + bv1,
                            acc[mt][nt][2] + bv0, acc[mt][nt][3] + bv1);
            }
        __syncthreads();
        // w2: x += h @ w2 + b2
        copyW(Wu, 3 + blk * 2, tid);
        __syncthreads();
        zero_acc(acc);
        gemm(Wu, Xu, acc, wm, wn, lane);
        __syncthreads();
        const float* bb2 = bias_s + 128 * (2 + blk * 2);
        bool last = (blk == 1);
#pragma unroll
        for (int mt = 0; mt < 2; mt++)
#pragma unroll
            for (int nt = 0; nt < 4; nt++) {
                int c0 = wn * 32 + nt * 8 + lq * 2;
                int r0 = wm * 32 + mt * 16 + lr;
                float bv0 = bb2[c0], bv1 = bb2[c0 + 1];
                xres[mt][nt][0] += acc[mt][nt][0] + bv0;
                xres[mt][nt][1] += acc[mt][nt][1] + bv1;
                xres[mt][nt][2] += acc[mt][nt][2] + bv0;
                xres[mt][nt][3] += acc[mt][nt][3] + bv1;
                if (!last) {
                    writeX_tile(Xu, r0, c0 >> 1, xres[mt][nt][0], xres[mt][nt][1],
                                xres[mt][nt][2], xres[mt][nt][3]);
                } else {
                    Fs[r0 * FS_STRIDE + c0]           = fmaxf(xres[mt][nt][0], 0.f);
                    Fs[r0 * FS_STRIDE + c0 + 1]       = fmaxf(xres[mt][nt][1], 0.f);
                    Fs[(r0 + 8) * FS_STRIDE + c0]     = fmaxf(xres[mt][nt][2], 0.f);
                    Fs[(r0 + 8) * FS_STRIDE + c0 + 1] = fmaxf(xres[mt][nt][3], 0.f);
                }
            }
        if (last) break;
        __syncthreads();
    }
    // stage head weights into ows (beyond Fs end; W/X dead)
    for (int i = tid; i < 1792; i += 512) ows[i] = ow[i];
    __syncthreads();

    // ---- head: unnorm = relu(x) @ ow + ob ----
    {
        int t = tid & 127, hh = tid >> 7;    // hh 0..3
        int ch0 = hh * 4;
        int cnt = (hh == 3) ? 2 : 4;
        float a0 = 0.f, a1 = 0.f, a2 = 0.f, a3 = 0.f;
        const float* Xp = Fs + t * FS_STRIDE;
#pragma unroll 4
        for (int k = 0; k < 128; k++) {
            float xv = Xp[k];
            const float* wp = ows + k * 14 + ch0;
            a0 += xv * wp[0];
            a1 += xv * wp[1];
            if (hh != 3) { a2 += xv * wp[2]; a3 += xv * wp[3]; }
        }
        Un[t * 14 + ch0 + 0] = a0 + ob[ch0 + 0];
        Un[t * 14 + ch0 + 1] = a1 + ob[ch0 + 1];
        if (cnt == 4) {
            Un[t * 14 + ch0 + 2] = a2 + ob[ch0 + 2];
            Un[t * 14 + ch0 + 3] = a3 + ob[ch0 + 3];
        }
    }
    __syncthreads();

    // ---- normalize + write angles/unnorm ----
    for (int i = tid; i < 896; i += 512) {
        int t = i & 127, a = i >> 7;
        float sv = Un[t * 14 + 2 * a];
        float cv = Un[t * 14 + 2 * a + 1];
        float inv = rsqrtf(sv * sv + cv * cv + 1e-12f);
        int tok = tokBase + t;
        out[OUT_UN + tok * 14 + 2 * a]      = sv;
        out[OUT_UN + tok * 14 + 2 * a + 1]  = cv;
        out[OUT_ANG + tok * 14 + 2 * a]     = sv * inv;
        out[OUT_ANG + tok * 14 + 2 * a + 1] = cv * inv;
    }
}

// ---------------------------------------------------------------------------
// Kernel B: frames + atoms, tables in smem, 128 tokens/block (unchanged)
// ---------------------------------------------------------------------------

__device__ __forceinline__ void compose34(float* __restrict__ o,
                                          const float* __restrict__ A,
                                          const float* __restrict__ Bm) {
#pragma unroll
    for (int r = 0; r < 3; r++) {
        float a0 = A[r*4+0], a1 = A[r*4+1], a2 = A[r*4+2], a3 = A[r*4+3];
#pragma unroll
        for (int c = 0; c < 3; c++)
            o[r*4+c] = a0 * Bm[c] + a1 * Bm[4+c] + a2 * Bm[8+c];
        o[r*4+3] = a0 * Bm[3] + a1 * Bm[7] + a2 * Bm[11] + a3;
    }
}

__global__ void __launch_bounds__(256) frames_kernel(
    const int* __restrict__ seq, const float* __restrict__ backb,
    const float* __restrict__ dframes, const int* __restrict__ gidx,
    const float* __restrict__ amask, const float* __restrict__ lit,
    float* __restrict__ out)
{
    __shared__ float sdf[21 * 8 * 16];
    __shared__ float slit[21 * 14 * 3];
    __shared__ float sam[21 * 14];
    __shared__ int   sgi[21 * 14];
    __shared__ float saf[32][8][12];

    const int tid = threadIdx.x;
    for (int i = tid; i < 2688; i += 256) sdf[i] = dframes[i];
    for (int i = tid; i < 882; i += 256) slit[i] = lit[i];
    for (int i = tid; i < 294; i += 256) { sam[i] = amask[i]; sgi[i] = gidx[i]; }
    __syncthreads();

    const int g = tid & 7;
    const int tl = tid >> 3;

#pragma unroll 1
    for (int it = 0; it < 4; it++) {
        const int tok = blockIdx.x * 128 + it * 32 + tl;
        const int s = seq[tok];

        float sv, cv;
        if (g == 0) { sv = 0.f; cv = 1.f; }
        else {
            sv = out[OUT_ANG + tok * 14 + (g - 1) * 2];
            cv = out[OUT_ANG + tok * 14 + (g - 1) * 2 + 1];
        }

        const float* df = sdf + (s * 8 + g) * 16;
        float F[12];
#pragma unroll
        for (int r = 0; r < 3; r++) {
            float m0 = df[r*4+0], m1 = df[r*4+1], m2 = df[r*4+2], m3 = df[r*4+3];
            F[r*4+0] = m0;
            F[r*4+1] = cv * m1 + sv * m2;
            F[r*4+2] = cv * m2 - sv * m1;
            F[r*4+3] = m3;
        }
#pragma unroll
        for (int i = 0; i < 12; i++) saf[tl][g][i] = F[i];
        __syncthreads();

        if (g == 0) {
            float A[12], Bm[12], Cm[12];
#pragma unroll
            for (int i = 0; i < 12; i++) A[i] = saf[tl][4][i];
#pragma unroll
            for (int i = 0; i < 12; i++) Bm[i] = saf[tl][5][i];
            compose34(Cm, A, Bm);
#pragma unroll
            for (int i = 0; i < 12; i++) saf[tl][5][i] = Cm[i];
#pragma unroll
            for (int i = 0; i < 12; i++) Bm[i] = saf[tl][6][i];
            compose34(A, Cm, Bm);
#pragma unroll
            for (int i = 0; i < 12; i++) saf[tl][6][i] = A[i];
#pragma unroll
            for (int i = 0; i < 12; i++) Bm[i] = saf[tl][7][i];
            compose34(Cm, A, Bm);
#pragma unroll
            for (int i = 0; i < 12; i++) saf[tl][7][i] = Cm[i];
        }
        __syncthreads();

        {
            const float4* bk4 = (const float4*)(backb + (size_t)tok * 16);
            float Bk[12], L[12], G[12];
            float4 b0 = bk4[0], b1v = bk4[1], b2v = bk4[2];
            Bk[0]=b0.x; Bk[1]=b0.y; Bk[2]=b0.z;  Bk[3]=b0.w;
            Bk[4]=b1v.x; Bk[5]=b1v.y; Bk[6]=b1v.z; Bk[7]=b1v.w;
            Bk[8]=b2v.x; Bk[9]=b2v.y; Bk[10]=b2v.z; Bk[11]=b2v.w;
#pragma unroll
            for (int i = 0; i < 12; i++) L[i] = saf[tl][g][i];
            compose34(G, Bk, L);
            float* o = out + OUT_ATG + (size_t)tok * 128 + g * 16;
            ((float4*)o)[0] = make_float4(G[0], G[1], G[2], G[3]);
            ((float4*)o)[1] = make_float4(G[4], G[5], G[6], G[7]);
            ((float4*)o)[2] = make_float4(G[8], G[9], G[10], G[11]);
            ((float4*)o)[3] = make_float4(0.f, 0.f, 0.f, 1.f);
#pragma unroll
            for (int i = 0; i < 12; i++) saf[tl][g][i] = G[i];
        }
        __syncthreads();

        for (int i = tid; i < 448; i += 256) {
            int t2 = i / 14;
            int a = i % 14;
            int tok2 = blockIdx.x * 128 + it * 32 + t2;
            int s2 = seq[tok2];
            int idx = s2 * 14 + a;
            int gg = sgi[idx];
            float m = sam[idx];
            float lx = slit[idx*3+0], ly = slit[idx*3+1], lz = slit[idx*3+2];
            const float* Fp = saf[t2][gg];
            float px = (Fp[0]*lx + Fp[1]*ly + Fp[2]*lz  + Fp[3])  * m;
            float py = (Fp[4]*lx + Fp[5]*ly + Fp[6]*lz  + Fp[7])  * m;
            float pz = (Fp[8]*lx + Fp[9]*ly + Fp[10]*lz + Fp[11]) * m;
            float* po = out + OUT_POS + (size_t)tok2 * 42 + a * 3;
            po[0] = px; po[1] = py; po[2] = pz;
        }
        __syncthreads();
    }
}

// ---------------------------------------------------------------------------

extern "C" void kernel_launch(void* const* d_in, const int* in_sizes, int n_in,
                              void* d_out, int out_size) {
    const int*   seq      = (const int*)  d_in[0];
    const float* backb    = (const float*)d_in[1];
    const float* act      = (const float*)d_in[2];
    const float* init_act = (const float*)d_in[3];
    const float* Wa       = (const float*)d_in[4];
    const float* ba       = (const float*)d_in[5];
    const float* Wi       = (const float*)d_in[6];
    const float* bi       = (const float*)d_in[7];
    const float* w1       = (const float*)d_in[8];
    const float* b1       = (const float*)d_in[9];
    const float* w2       = (const float*)d_in[10];
    const float* b2       = (const float*)d_in[11];
    const float* ow       = (const float*)d_in[12];
    const float* ob       = (const float*)d_in[13];
    const float* dframes  = (const float*)d_in[14];
    const int*   gidx     = (const int*)  d_in[15];
    const float* amask    = (const float*)d_in[16];
    const float* lit      = (const float*)d_in[17];
    float* out = (float*)d_out;

    cudaFuncSetAttribute(mlp_kernel, cudaFuncAttributeMaxDynamicSharedMemorySize, SM_TOT);

    prep_kernel<<<384, 256>>>(Wa, Wi, w1, w2);
    mlp_kernel<<<NTOK / 128, 512, SM_TOT>>>(act, init_act, ba, bi, b1, b2, ow, ob, out);
    frames_kernel<<<NTOK / 128, 256>>>(seq, backb, dframes, gidx, amask, lit, out);
}

// round 9
// speedup vs baseline: 1.5134x; 1.0692x over previous
#include <cuda_runtime.h>
#include <cuda_bf16.h>
#include <cstdint>

#define NTOK 65536
#define OUT_ANG 0
#define OUT_UN  (NTOK*14)
#define OUT_POS (2*NTOK*14)
#define OUT_ATG (2*NTOK*14 + NTOK*42)

// row stride in uint2 (8B) units: 68 -> half-warp bank-pair (4*lr+lq) mod 16 distinct
#define XSTRIDE 68
#define LAYER_U2 (128 * XSTRIDE)            // 8704 uint2 = 69632 B per W tile

// smem byte offsets (mlp kernel, 64 tokens/CTA)
#define SM_W    0                           // 69632 B
#define SM_X    69632                       // 34816 B (64 rows)
#define SM_BIAS 104448                      // 2560 B
#define SM_UNB  107008                      // 3584 B (64 x 14)
#define SM_TOT  110592                      // 108 KB -> 2 CTAs/SM
// aliases (used only after the last GEMM):
#define FS_STRIDE 129                       // final activations fp32 @ byte 0 (33024 B)
#define SM_OWS  36864                       // head weights (1792 floats) inside W region

// pre-split weights: 6 layers, padded smem image (stride 68)
__device__ unsigned short wbuf16[6 * LAYER_U2 * 4];

__device__ __forceinline__ void mma_bf16(float c[4], uint32_t a0, uint32_t a1,
                                         uint32_t a2, uint32_t a3,
                                         uint32_t b0, uint32_t b1) {
    asm("mma.sync.aligned.m16n8k16.row.col.f32.bf16.bf16.f32 "
        "{%0,%1,%2,%3}, {%4,%5,%6,%7}, {%8,%9}, {%0,%1,%2,%3};"
        : "+f"(c[0]), "+f"(c[1]), "+f"(c[2]), "+f"(c[3])
        : "r"(a0), "r"(a1), "r"(a2), "r"(a3), "r"(b0), "r"(b1));
}

// pack (x0 -> low, x1 -> high) into bf16x2 hi, and residual lo
__device__ __forceinline__ void packHiLo(float x0, float x1,
                                         uint32_t& hi2, uint32_t& lo2) {
    asm("cvt.rn.bf16x2.f32 %0,%1,%2;" : "=r"(hi2) : "f"(x1), "f"(x0));
    float h0 = __uint_as_float(hi2 << 16);
    float h1 = __uint_as_float(hi2 & 0xFFFF0000u);
    asm("cvt.rn.bf16x2.f32 %0,%1,%2;" : "=r"(lo2) : "f"(x1 - h1), "f"(x0 - h0));
}

// ---------------------------------------------------------------------------
// prep kernel (unchanged layout)
// ---------------------------------------------------------------------------
__global__ void prep_kernel(const float* __restrict__ Wa, const float* __restrict__ Wi,
                            const float* __restrict__ w1, const float* __restrict__ w2) {
    int layer = blockIdx.x >> 6;
    int e = ((blockIdx.x & 63) << 8) + threadIdx.x;   // 0..16383
    const float* src;
    switch (layer) {
        case 0: src = Wa; break;
        case 1: src = Wi; break;
        case 2: src = w1; break;
        case 3: src = w2; break;
        case 4: src = w1 + 16384; break;
        default: src = w2 + 16384; break;
    }
    float w = src[e];
    int k = e >> 7, n = e & 127;
    __nv_bfloat16 hb = __float2bfloat16_rn(w);
    unsigned short hibits = __bfloat16_as_ushort(hb);
    float hf = __uint_as_float(((uint32_t)hibits) << 16);
    unsigned short lobits = __bfloat16_as_ushort(__float2bfloat16_rn(w - hf));
    int p = k >> 1, half = k & 1;
    unsigned short* dst = wbuf16 + ((size_t)layer * LAYER_U2 + n * XSTRIDE + p) * 4;
    dst[half]     = hibits;
    dst[2 + half] = lobits;
}

// ---------------------------------------------------------------------------
// MLP kernel: 64 tokens/CTA, 256 threads (8 warps, 2x4), 2 CTAs/SM.
// ---------------------------------------------------------------------------

__device__ __forceinline__ void stageX_relu(uint2* __restrict__ Xu,
                                            const float* __restrict__ g,
                                            int tokBase, int tid) {
    const float4* src = (const float4*)g;
#pragma unroll
    for (int i = 0; i < 8; i++) {
        int idx4 = tid + i * 256;          // 0..2047
        int row = idx4 >> 5;               // 0..63
        int q = idx4 & 31;
        float4 v = src[(size_t)(tokBase + row) * 32 + q];
        float r0 = fmaxf(v.x, 0.f), r1 = fmaxf(v.y, 0.f);
        float r2 = fmaxf(v.z, 0.f), r3 = fmaxf(v.w, 0.f);
        uint2 e0, e1;
        packHiLo(r0, r1, e0.x, e0.y);
        packHiLo(r2, r3, e1.x, e1.y);
        Xu[row * XSTRIDE + 2 * q]     = e0;
        Xu[row * XSTRIDE + 2 * q + 1] = e1;
    }
}

__device__ __forceinline__ void copyW(void* Wsm, int layer, int tid) {
    const float4* src = (const float4*)(wbuf16 + (size_t)layer * LAYER_U2 * 4);
    float4* dst = (float4*)Wsm;
    // 4352 float4 / 256 threads = 17 each
#pragma unroll
    for (int i = 0; i < 17; i++) dst[tid + i * 256] = src[tid + i * 256];
}

// 64x128x128 GEMM: acc += X @ W (3-pass bf16 emulation)
__device__ __forceinline__ void gemm(const uint2* __restrict__ Wu,
                                     const uint2* __restrict__ Xu,
                                     float acc[2][4][4], int wm, int wn, int lane) {
    const int lq = lane & 3, lr = lane >> 2;
#pragma unroll 2
    for (int kk = 0; kk < 8; kk++) {
        const int p0 = kk * 8 + lq;
        const int p1 = kk * 8 + 4 + lq;
        uint32_t ahi[2][4], alo[2][4];
#pragma unroll
        for (int mt = 0; mt < 2; mt++) {
            int r0 = (wm * 32 + mt * 16 + lr) * XSTRIDE;
            uint2 v0 = Xu[r0 + p0];
            uint2 v1 = Xu[r0 + 8 * XSTRIDE + p0];
            uint2 v2 = Xu[r0 + p1];
            uint2 v3 = Xu[r0 + 8 * XSTRIDE + p1];
            ahi[mt][0] = v0.x; alo[mt][0] = v0.y;
            ahi[mt][1] = v1.x; alo[mt][1] = v1.y;
            ahi[mt][2] = v2.x; alo[mt][2] = v2.y;
            ahi[mt][3] = v3.x; alo[mt][3] = v3.y;
        }
#pragma unroll
        for (int nt = 0; nt < 4; nt++) {
            int n = (wn * 32 + nt * 8 + lr) * XSTRIDE;
            uint2 b0 = Wu[n + p0];
            uint2 b1 = Wu[n + p1];
#pragma unroll
            for (int mt = 0; mt < 2; mt++) {
                mma_bf16(acc[mt][nt], ahi[mt][0], ahi[mt][1], ahi[mt][2], ahi[mt][3], b0.x, b1.x);
                mma_bf16(acc[mt][nt], alo[mt][0], alo[mt][1], alo[mt][2], alo[mt][3], b0.x, b1.x);
                mma_bf16(acc[mt][nt], ahi[mt][0], ahi[mt][1], ahi[mt][2], ahi[mt][3], b0.y, b1.y);
            }
        }
    }
}

__device__ __forceinline__ void zero_acc(float acc[2][4][4]) {
#pragma unroll
    for (int mt = 0; mt < 2; mt++)
#pragma unroll
        for (int nt = 0; nt < 4; nt++)
#pragma unroll
            for (int d = 0; d < 4; d++) acc[mt][nt][d] = 0.f;
}

__device__ __forceinline__ void writeX_tile(uint2* __restrict__ Xu, int r0, int p,
                                            float v0, float v1, float v2, float v3) {
    uint2 e;
    packHiLo(fmaxf(v0, 0.f), fmaxf(v1, 0.f), e.x, e.y);
    Xu[r0 * XSTRIDE + p] = e;
    packHiLo(fmaxf(v2, 0.f), fmaxf(v3, 0.f), e.x, e.y);
    Xu[(r0 + 8) * XSTRIDE + p] = e;
}

__global__ void __launch_bounds__(256, 2) mlp_kernel(
    const float* __restrict__ act, const float* __restrict__ init_act,
    const float* __restrict__ ba, const float* __restrict__ bi,
    const float* __restrict__ b1, const float* __restrict__ b2,
    const float* __restrict__ ow, const float* __restrict__ ob,
    float* __restrict__ out)
{
    extern __shared__ __align__(16) char smem[];
    uint2* Wu = (uint2*)(smem + SM_W);
    uint2* Xu = (uint2*)(smem + SM_X);
    float* bias_s = (float*)(smem + SM_BIAS);
    float* Un  = (float*)(smem + SM_UNB);
    float* Fs  = (float*)smem;               // alias over W region, post-GEMM only
    float* ows = (float*)(smem + SM_OWS);

    const int tid = threadIdx.x;
    const int lane = tid & 31;
    const int wid = tid >> 5;
    const int wm = wid >> 2, wn = wid & 3;   // 2 x 4 warp grid
    const int lq = lane & 3, lr = lane >> 2;
    const int tokBase = blockIdx.x * 64;

    // bias staging: 0=ba+bi, 1=b1[0], 2=b2[0], 3=b1[1], 4=b2[1]
    for (int i = tid; i < 640; i += 256) {
        int slot = i >> 7, c = i & 127;
        float v;
        if (slot == 0)      v = ba[c] + bi[c];
        else if (slot == 1) v = b1[c];
        else if (slot == 2) v = b2[c];
        else if (slot == 3) v = b1[128 + c];
        else                v = b2[128 + c];
        bias_s[i] = v;
    }

    float acc[2][4][4], xres[2][4][4];

    // ---- layer 1a: relu(act) @ Wa ----
    stageX_relu(Xu, act, tokBase, tid);
    copyW(Wu, 0, tid);
    __syncthreads();
    zero_acc(acc);
    gemm(Wu, Xu, acc, wm, wn, lane);
    __syncthreads();

    // ---- layer 1b: += relu(init_act) @ Wi ----
    stageX_relu(Xu, init_act, tokBase, tid);
    copyW(Wu, 1, tid);
    __syncthreads();
    gemm(Wu, Xu, acc, wm, wn, lane);
    __syncthreads();

    // epilogue 1: xres = acc + bias0; X <- relu(xres)
#pragma unroll
    for (int mt = 0; mt < 2; mt++)
#pragma unroll
        for (int nt = 0; nt < 4; nt++) {
            int c0 = wn * 32 + nt * 8 + lq * 2;
            int r0 = wm * 32 + mt * 16 + lr;
            float bv0 = bias_s[c0], bv1 = bias_s[c0 + 1];
            xres[mt][nt][0] = acc[mt][nt][0] + bv0;
            xres[mt][nt][1] = acc[mt][nt][1] + bv1;
            xres[mt][nt][2] = acc[mt][nt][2] + bv0;
            xres[mt][nt][3] = acc[mt][nt][3] + bv1;
            writeX_tile(Xu, r0, c0 >> 1, xres[mt][nt][0], xres[mt][nt][1],
                        xres[mt][nt][2], xres[mt][nt][3]);
        }

    // ---- resnet blocks ----
#pragma unroll 1
    for (int blk = 0; blk < 2; blk++) {
        copyW(Wu, 2 + blk * 2, tid);
        __syncthreads();
        zero_acc(acc);
        gemm(Wu, Xu, acc, wm, wn, lane);
        __syncthreads();
        const float* bb1 = bias_s + 128 * (1 + blk * 2);
#pragma unroll
        for (int mt = 0; mt < 2; mt++)
#pragma unroll
            for (int nt = 0; nt < 4; nt++) {
                int c0 = wn * 32 + nt * 8 + lq * 2;
                int r0 = wm * 32 + mt * 16 + lr;
                float bv0 = bb1[c0], bv1 = bb1[c0 + 1];
                writeX_tile(Xu, r0, c0 >> 1, acc[mt][nt][0] + bv0, acc[mt][nt][1] + bv1,
                            acc[mt][nt][2] + bv0, acc[mt][nt][3] + bv1);
            }
        __syncthreads();
        copyW(Wu, 3 + blk * 2, tid);
        __syncthreads();
        zero_acc(acc);
        gemm(Wu, Xu, acc, wm, wn, lane);
        __syncthreads();
        const float* bb2 = bias_s + 128 * (2 + blk * 2);
        bool last = (blk == 1);
#pragma unroll
        for (int mt = 0; mt < 2; mt++)
#pragma unroll
            for (int nt = 0; nt < 4; nt++) {
                int c0 = wn * 32 + nt * 8 + lq * 2;
                int r0 = wm * 32 + mt * 16 + lr;
                float bv0 = bb2[c0], bv1 = bb2[c0 + 1];
                xres[mt][nt][0] += acc[mt][nt][0] + bv0;
                xres[mt][nt][1] += acc[mt][nt][1] + bv1;
                xres[mt][nt][2] += acc[mt][nt][2] + bv0;
                xres[mt][nt][3] += acc[mt][nt][3] + bv1;
                if (!last) {
                    writeX_tile(Xu, r0, c0 >> 1, xres[mt][nt][0], xres[mt][nt][1],
                                xres[mt][nt][2], xres[mt][nt][3]);
                } else {
                    Fs[r0 * FS_STRIDE + c0]           = fmaxf(xres[mt][nt][0], 0.f);
                    Fs[r0 * FS_STRIDE + c0 + 1]       = fmaxf(xres[mt][nt][1], 0.f);
                    Fs[(r0 + 8) * FS_STRIDE + c0]     = fmaxf(xres[mt][nt][2], 0.f);
                    Fs[(r0 + 8) * FS_STRIDE + c0 + 1] = fmaxf(xres[mt][nt][3], 0.f);
                }
            }
        if (last) break;
        __syncthreads();
    }
    // stage head weights into ows (inside dead W region, beyond Fs end)
    for (int i = tid; i < 1792; i += 256) ows[i] = ow[i];
    __syncthreads();

    // ---- head: unnorm = relu(x) @ ow + ob ----
    {
        int t = tid & 63, hh = tid >> 6;     // hh 0..3
        int ch0 = hh * 4;
        int cnt = (hh == 3) ? 2 : 4;
        float a0 = 0.f, a1 = 0.f, a2 = 0.f, a3 = 0.f;
        const float* Xp = Fs + t * FS_STRIDE;
#pragma unroll 4
        for (int k = 0; k < 128; k++) {
            float xv = Xp[k];
            const float* wp = ows + k * 14 + ch0;
            a0 += xv * wp[0];
            a1 += xv * wp[1];
            if (hh != 3) { a2 += xv * wp[2]; a3 += xv * wp[3]; }
        }
        Un[t * 14 + ch0 + 0] = a0 + ob[ch0 + 0];
        Un[t * 14 + ch0 + 1] = a1 + ob[ch0 + 1];
        if (cnt == 4) {
            Un[t * 14 + ch0 + 2] = a2 + ob[ch0 + 2];
            Un[t * 14 + ch0 + 3] = a3 + ob[ch0 + 3];
        }
    }
    __syncthreads();

    // ---- normalize + write angles/unnorm ----
    for (int i = tid; i < 448; i += 256) {
        int t = i & 63, a = i >> 6;          // a 0..6
        float sv = Un[t * 14 + 2 * a];
        float cv = Un[t * 14 + 2 * a + 1];
        float inv = rsqrtf(sv * sv + cv * cv + 1e-12f);
        int tok = tokBase + t;
        out[OUT_UN + tok * 14 + 2 * a]      = sv;
        out[OUT_UN + tok * 14 + 2 * a + 1]  = cv;
        out[OUT_ANG + tok * 14 + 2 * a]     = sv * inv;
        out[OUT_ANG + tok * 14 + 2 * a + 1] = cv * inv;
    }
}

// ---------------------------------------------------------------------------
// Kernel B: frames + atoms, tables in smem, 128 tokens/block (unchanged)
// ---------------------------------------------------------------------------

__device__ __forceinline__ void compose34(float* __restrict__ o,
                                          const float* __restrict__ A,
                                          const float* __restrict__ Bm) {
#pragma unroll
    for (int r = 0; r < 3; r++) {
        float a0 = A[r*4+0], a1 = A[r*4+1], a2 = A[r*4+2], a3 = A[r*4+3];
#pragma unroll
        for (int c = 0; c < 3; c++)
            o[r*4+c] = a0 * Bm[c] + a1 * Bm[4+c] + a2 * Bm[8+c];
        o[r*4+3] = a0 * Bm[3] + a1 * Bm[7] + a2 * Bm[11] + a3;
    }
}

__global__ void __launch_bounds__(256) frames_kernel(
    const int* __restrict__ seq, const float* __restrict__ backb,
    const float* __restrict__ dframes, const int* __restrict__ gidx,
    const float* __restrict__ amask, const float* __restrict__ lit,
    float* __restrict__ out)
{
    __shared__ float sdf[21 * 8 * 16];
    __shared__ float slit[21 * 14 * 3];
    __shared__ float sam[21 * 14];
    __shared__ int   sgi[21 * 14];
    __shared__ float saf[32][8][12];

    const int tid = threadIdx.x;
    for (int i = tid; i < 2688; i += 256) sdf[i] = dframes[i];
    for (int i = tid; i < 882; i += 256) slit[i] = lit[i];
    for (int i = tid; i < 294; i += 256) { sam[i] = amask[i]; sgi[i] = gidx[i]; }
    __syncthreads();

    const int g = tid & 7;
    const int tl = tid >> 3;

#pragma unroll 1
    for (int it = 0; it < 4; it++) {
        const int tok = blockIdx.x * 128 + it * 32 + tl;
        const int s = seq[tok];

        float sv, cv;
        if (g == 0) { sv = 0.f; cv = 1.f; }
        else {
            sv = out[OUT_ANG + tok * 14 + (g - 1) * 2];
            cv = out[OUT_ANG + tok * 14 + (g - 1) * 2 + 1];
        }

        const float* df = sdf + (s * 8 + g) * 16;
        float F[12];
#pragma unroll
        for (int r = 0; r < 3; r++) {
            float m0 = df[r*4+0], m1 = df[r*4+1], m2 = df[r*4+2], m3 = df[r*4+3];
            F[r*4+0] = m0;
            F[r*4+1] = cv * m1 + sv * m2;
            F[r*4+2] = cv * m2 - sv * m1;
            F[r*4+3] = m3;
        }
#pragma unroll
        for (int i = 0; i < 12; i++) saf[tl][g][i] = F[i];
        __syncthreads();

        if (g == 0) {
            float A[12], Bm[12], Cm[12];
#pragma unroll
            for (int i = 0; i < 12; i++) A[i] = saf[tl][4][i];
#pragma unroll
            for (int i = 0; i < 12; i++) Bm[i] = saf[tl][5][i];
            compose34(Cm, A, Bm);
#pragma unroll
            for (int i = 0; i < 12; i++) saf[tl][5][i] = Cm[i];
#pragma unroll
            for (int i = 0; i < 12; i++) Bm[i] = saf[tl][6][i];
            compose34(A, Cm, Bm);
#pragma unroll
            for (int i = 0; i < 12; i++) saf[tl][6][i] = A[i];
#pragma unroll
            for (int i = 0; i < 12; i++) Bm[i] = saf[tl][7][i];
            compose34(Cm, A, Bm);
#pragma unroll
            for (int i = 0; i < 12; i++) saf[tl][7][i] = Cm[i];
        }
        __syncthreads();

        {
            const float4* bk4 = (const float4*)(backb + (size_t)tok * 16);
            float Bk[12], L[12], G[12];
            float4 b0 = bk4[0], b1v = bk4[1], b2v = bk4[2];
            Bk[0]=b0.x; Bk[1]=b0.y; Bk[2]=b0.z;  Bk[3]=b0.w;
            Bk[4]=b1v.x; Bk[5]=b1v.y; Bk[6]=b1v.z; Bk[7]=b1v.w;
            Bk[8]=b2v.x; Bk[9]=b2v.y; Bk[10]=b2v.z; Bk[11]=b2v.w;
#pragma unroll
            for (int i = 0; i < 12; i++) L[i] = saf[tl][g][i];
            compose34(G, Bk, L);
            float* o = out + OUT_ATG + (size_t)tok * 128 + g * 16;
            ((float4*)o)[0] = make_float4(G[0], G[1], G[2], G[3]);
            ((float4*)o)[1] = make_float4(G[4], G[5], G[6], G[7]);
            ((float4*)o)[2] = make_float4(G[8], G[9], G[10], G[11]);
            ((float4*)o)[3] = make_float4(0.f, 0.f, 0.f, 1.f);
#pragma unroll
            for (int i = 0; i < 12; i++) saf[tl][g][i] = G[i];
        }
        __syncthreads();

        for (int i = tid; i < 448; i += 256) {
            int t2 = i / 14;
            int a = i % 14;
            int tok2 = blockIdx.x * 128 + it * 32 + t2;
            int s2 = seq[tok2];
            int idx = s2 * 14 + a;
            int gg = sgi[idx];
            float m = sam[idx];
            float lx = slit[idx*3+0], ly = slit[idx*3+1], lz = slit[idx*3+2];
            const float* Fp = saf[t2][gg];
            float px = (Fp[0]*lx + Fp[1]*ly + Fp[2]*lz  + Fp[3])  * m;
            float py = (Fp[4]*lx + Fp[5]*ly + Fp[6]*lz  + Fp[7])  * m;
            float pz = (Fp[8]*lx + Fp[9]*ly + Fp[10]*lz + Fp[11]) * m;
            float* po = out + OUT_POS + (size_t)tok2 * 42 + a * 3;
            po[0] = px; po[1] = py; po[2] = pz;
        }
        __syncthreads();
    }
}

// ---------------------------------------------------------------------------

extern "C" void kernel_launch(void* const* d_in, const int* in_sizes, int n_in,
                              void* d_out, int out_size) {
    const int*   seq      = (const int*)  d_in[0];
    const float* backb    = (const float*)d_in[1];
    const float* act      = (const float*)d_in[2];
    const float* init_act = (const float*)d_in[3];
    const float* Wa       = (const float*)d_in[4];
    const float* ba       = (const float*)d_in[5];
    const float* Wi       = (const float*)d_in[6];
    const float* bi       = (const float*)d_in[7];
    const float* w1       = (const float*)d_in[8];
    const float* b1       = (const float*)d_in[9];
    const float* w2       = (const float*)d_in[10];
    const float* b2       = (const float*)d_in[11];
    const float* ow       = (const float*)d_in[12];
    const float* ob       = (const float*)d_in[13];
    const float* dframes  = (const float*)d_in[14];
    const int*   gidx     = (const int*)  d_in[15];
    const float* amask    = (const float*)d_in[16];
    const float* lit      = (const float*)d_in[17];
    float* out = (float*)d_out;

    cudaFuncSetAttribute(mlp_kernel, cudaFuncAttributeMaxDynamicSharedMemorySize, SM_TOT);

    prep_kernel<<<384, 256>>>(Wa, Wi, w1, w2);
    mlp_kernel<<<NTOK / 64, 256, SM_TOT>>>(act, init_act, ba, bi, b1, b2, ow, ob, out);
    frames_kernel<<<NTOK / 128, 256>>>(seq, backb, dframes, gidx, amask, lit, out);
}

// round 11
// speedup vs baseline: 1.6117x; 1.0650x over previous
#include <cuda_runtime.h>
#include <cstdint>

#define NTOK 65536
#define OUT_ANG 0
#define OUT_UN  (NTOK*14)
#define OUT_POS (2*NTOK*14)
#define OUT_ATG (2*NTOK*14 + NTOK*42)

#define XQS 36                 // row stride in uint2 {c1word, c2word}; 32 words + 4 pad
#define LAYER_U2 (128 * XQS)   // 4608 uint2 per W layer image

// smem byte offsets
#define SM_W    0              // 36864 B: W quantized image
#define SM_X    36864          // 18432 B: X quantized (64 rows x 36 uint2)
#define SM_SB   55296          // 3072 B : 6 x 128 weight col scales
#define SM_BIAS 58368          // 2560 B : 5 x 128 bias
#define SM_SROW 60928          // 512 B  : 2 x 64 row scales
#define SM_INV  61440          // 256 B  : 64 inverse scales
#define SM_RMP  61696          // 1024 B : 4 x 64 rowmax partials
#define SM_UNB  62720          // 3584 B : 64 x 14 unnorm
#define SM_TOT  66304
// post-GEMM aliases over W/X region:
#define FS_STRIDE 129          // 64 x 129 fp32 @ 0 (33024 B)
#define SM_OWS  33024          // head weights (1792 floats)

__device__ uint2 wqbuf[6 * LAYER_U2];   // quantized weights (smem image)
__device__ float sbg[6 * 128];          // per-col weight scales

__device__ __forceinline__ void mma_s8(int c[4], uint32_t a0, uint32_t a1,
                                       uint32_t a2, uint32_t a3,
                                       uint32_t b0, uint32_t b1) {
    asm("mma.sync.aligned.m16n8k32.row.col.s32.s8.s8.s32 "
        "{%0,%1,%2,%3}, {%4,%5,%6,%7}, {%8,%9}, {%0,%1,%2,%3};"
        : "+r"(c[0]), "+r"(c[1]), "+r"(c[2]), "+r"(c[3])
        : "r"(a0), "r"(a1), "r"(a2), "r"(a3), "r"(b0), "r"(b1));
}

// split q (|q|<=8160) into c1*128+c2, return packed bytes for 4 lanes
__device__ __forceinline__ void split4(const int q[4], uint32_t& c1w, uint32_t& c2w) {
    uint32_t a = 0, b = 0;
#pragma unroll
    for (int i = 0; i < 4; i++) {
        int c1 = (q[i] + 64) >> 7;
        int c2 = q[i] - (c1 << 7);
        a |= (uint32_t)(c1 & 0xFF) << (8 * i);
        b |= (uint32_t)(c2 & 0xFF) << (8 * i);
    }
    c1w = a; c2w = b;
}

// ---------------------------------------------------------------------------
// prep1: per-layer per-col |max| -> scale.  prep2: quantize W into wqbuf.
// layer order: 0=Wa 1=Wi 2=w1[0] 3=w2[0] 4=w1[1] 5=w2[1]
// ---------------------------------------------------------------------------
__device__ __forceinline__ const float* layer_src(int layer,
    const float* Wa, const float* Wi, const float* w1, const float* w2) {
    switch (layer) {
        case 0: return Wa; case 1: return Wi; case 2: return w1;
        case 3: return w2; case 4: return w1 + 16384; default: return w2 + 16384;
    }
}

__global__ void prep1(const float* __restrict__ Wa, const float* __restrict__ Wi,
                      const float* __restrict__ w1, const float* __restrict__ w2) {
    const float* src = layer_src(blockIdx.x, Wa, Wi, w1, w2);
    int n = threadIdx.x;
    float m = 0.f;
    for (int k = 0; k < 128; k++) m = fmaxf(m, fabsf(src[k * 128 + n]));
    sbg[blockIdx.x * 128 + n] = fmaxf(m, 1e-20f) * (1.f / 8160.f);
}

__global__ void prep2(const float* __restrict__ Wa, const float* __restrict__ Wi,
                      const float* __restrict__ w1, const float* __restrict__ w2) {
    int layer = blockIdx.x >> 7, n = blockIdx.x & 127;
    const float* src = layer_src(layer, Wa, Wi, w1, w2);
    float inv = 1.f / sbg[blockIdx.x];
    int w = threadIdx.x;                    // word 0..31
    int q[4];
#pragma unroll
    for (int i = 0; i < 4; i++)
        q[i] = __float2int_rn(src[(w * 4 + i) * 128 + n] * inv);
    uint32_t c1w, c2w;
    split4(q, c1w, c2w);
    wqbuf[(size_t)layer * LAYER_U2 + n * XQS + w] = make_uint2(c1w, c2w);
}

// ---------------------------------------------------------------------------
// MLP kernel: 64 tokens/CTA, 256 threads (8 warps 2x4), int8 2-chunk mma.
// ---------------------------------------------------------------------------

// stage + relu + quantize gmem activations; each warp handles full rows
__device__ __forceinline__ void stageX_quant(uint2* __restrict__ Xq,
                                             const float* __restrict__ g,
                                             int tokBase, int tid,
                                             float* __restrict__ srow_out) {
    int w = tid >> 5, l = tid & 31;
    const float4* src = (const float4*)g;
#pragma unroll
    for (int i = 0; i < 8; i++) {
        int row = w + 8 * i;
        float4 v = src[(size_t)(tokBase + row) * 32 + l];
        float r0 = fmaxf(v.x, 0.f), r1 = fmaxf(v.y, 0.f);
        float r2 = fmaxf(v.z, 0.f), r3 = fmaxf(v.w, 0.f);
        float lm = fmaxf(fmaxf(r0, r1), fmaxf(r2, r3));
#pragma unroll
        for (int off = 16; off >= 1; off >>= 1)
            lm = fmaxf(lm, __shfl_xor_sync(0xFFFFFFFFu, lm, off));
        lm = fmaxf(lm, 1e-20f);
        float inv = 8160.f / lm;
        if (l == 0) srow_out[row] = lm * (1.f / 8160.f);
        int q[4] = { __float2int_rn(r0 * inv), __float2int_rn(r1 * inv),
                     __float2int_rn(r2 * inv), __float2int_rn(r3 * inv) };
        uint32_t c1w, c2w;
        split4(q, c1w, c2w);
        Xq[row * XQS + l] = make_uint2(c1w, c2w);
    }
}

__device__ __forceinline__ void copyW(void* Wsm, int layer, int tid) {
    const float4* src = (const float4*)(wqbuf + (size_t)layer * LAYER_U2);
    float4* dst = (float4*)Wsm;
#pragma unroll
    for (int i = 0; i < 9; i++) dst[tid + i * 256] = src[tid + i * 256];
}

__device__ __forceinline__ void zeroP(int P1[2][4][4], int P23[2][4][4]) {
#pragma unroll
    for (int mt = 0; mt < 2; mt++)
#pragma unroll
        for (int nt = 0; nt < 4; nt++)
#pragma unroll
            for (int d = 0; d < 4; d++) { P1[mt][nt][d] = 0; P23[mt][nt][d] = 0; }
}

// 64x128x128 int8 GEMM: P1 += c1a*c1b ; P23 += c1a*c2b + c2a*c1b
__device__ __forceinline__ void gemm(const uint2* __restrict__ Wq,
                                     const uint2* __restrict__ Xq,
                                     int P1[2][4][4], int P23[2][4][4],
                                     int wm, int wn, int lane) {
    const int lq = lane & 3, lr = lane >> 2;
#pragma unroll
    for (int kk = 0; kk < 4; kk++) {
        const int p0 = kk * 8 + lq;
        const int p1 = p0 + 4;
        uint32_t a1[2][4], a2[2][4];
#pragma unroll
        for (int mt = 0; mt < 2; mt++) {
            int r = (wm * 32 + mt * 16 + lr) * XQS;
            uint2 v0 = Xq[r + p0];
            uint2 v1 = Xq[r + 8 * XQS + p0];
            uint2 v2 = Xq[r + p1];
            uint2 v3 = Xq[r + 8 * XQS + p1];
            a1[mt][0] = v0.x; a2[mt][0] = v0.y;
            a1[mt][1] = v1.x; a2[mt][1] = v1.y;
            a1[mt][2] = v2.x; a2[mt][2] = v2.y;
            a1[mt][3] = v3.x; a2[mt][3] = v3.y;
        }
#pragma unroll
        for (int nt = 0; nt < 4; nt++) {
            int n = (wn * 32 + nt * 8 + lr) * XQS;
            uint2 b0 = Wq[n + p0];
            uint2 b1 = Wq[n + p1];
#pragma unroll
            for (int mt = 0; mt < 2; mt++) {
                mma_s8(P1[mt][nt],  a1[mt][0], a1[mt][1], a1[mt][2], a1[mt][3], b0.x, b1.x);
                mma_s8(P23[mt][nt], a1[mt][0], a1[mt][1], a1[mt][2], a1[mt][3], b0.y, b1.y);
                mma_s8(P23[mt][nt], a2[mt][0], a2[mt][1], a2[mt][2], a2[mt][3], b0.x, b1.x);
            }
        }
    }
}

// dequant: res = srow[r] * sb[c] * (16384*P1 + 128*P23)
#define DEQ_VAL(mt, nt, d, r, c) \
    (fmaf(16384.f, (float)P1[mt][nt][d], 128.f * (float)P23[mt][nt][d]) * srp[r] * sbl[c])

__device__ __forceinline__ void qstore(char* __restrict__ Xq8, int r, int c,
                                       float v, float inv) {
    int q = __float2int_rn(v * inv);
    int c1 = (q + 64) >> 7;
    int c2 = q - (c1 << 7);
    int base = r * (XQS * 8) + ((c >> 2) << 3) + (c & 3);
    Xq8[base] = (char)c1;
    Xq8[base + 4] = (char)c2;
}

// quantize relu'd values vr into Xq; computes per-row scales into srow_out
__device__ __forceinline__ void quant_epi(float vr[2][4][4], char* __restrict__ Xq8,
                                          float* __restrict__ rmp,
                                          float* __restrict__ srow_out,
                                          float* __restrict__ invs,
                                          int wm, int wn, int lq, int lr, int tid) {
    float rm0[2], rm1[2];
#pragma unroll
    for (int mt = 0; mt < 2; mt++) {
        float m0 = 0.f, m1 = 0.f;
#pragma unroll
        for (int nt = 0; nt < 4; nt++) {
            m0 = fmaxf(m0, fmaxf(vr[mt][nt][0], vr[mt][nt][1]));
            m1 = fmaxf(m1, fmaxf(vr[mt][nt][2], vr[mt][nt][3]));
        }
        m0 = fmaxf(m0, __shfl_xor_sync(0xFFFFFFFFu, m0, 1));
        m0 = fmaxf(m0, __shfl_xor_sync(0xFFFFFFFFu, m0, 2));
        m1 = fmaxf(m1, __shfl_xor_sync(0xFFFFFFFFu, m1, 1));
        m1 = fmaxf(m1, __shfl_xor_sync(0xFFFFFFFFu, m1, 2));
        rm0[mt] = m0; rm1[mt] = m1;
    }
    if (lq == 0) {
#pragma unroll
        for (int mt = 0; mt < 2; mt++) {
            int r0 = wm * 32 + mt * 16 + lr;
            rmp[wn * 64 + r0] = rm0[mt];
            rmp[wn * 64 + r0 + 8] = rm1[mt];
        }
    }
    __syncthreads();
    if (tid < 64) {
        float m = fmaxf(fmaxf(rmp[tid], rmp[64 + tid]),
                        fmaxf(rmp[128 + tid], rmp[192 + tid]));
        m = fmaxf(m, 1e-20f);
        srow_out[tid] = m * (1.f / 8160.f);
        invs[tid] = 8160.f / m;
    }
    __syncthreads();
#pragma unroll
    for (int mt = 0; mt < 2; mt++)
#pragma unroll
        for (int nt = 0; nt < 4; nt++) {
            int r0 = wm * 32 + mt * 16 + lr;
            int c0 = wn * 32 + nt * 8 + lq * 2;
            float i0 = invs[r0], i8 = invs[r0 + 8];
            qstore(Xq8, r0, c0,     vr[mt][nt][0], i0);
            qstore(Xq8, r0, c0 + 1, vr[mt][nt][1], i0);
            qstore(Xq8, r0 + 8, c0,     vr[mt][nt][2], i8);
            qstore(Xq8, r0 + 8, c0 + 1, vr[mt][nt][3], i8);
        }
}

__global__ void __launch_bounds__(256, 2) mlp_kernel(
    const float* __restrict__ act, const float* __restrict__ init_act,
    const float* __restrict__ ba, const float* __restrict__ bi,
    const float* __restrict__ b1, const float* __restrict__ b2,
    const float* __restrict__ ow, const float* __restrict__ ob,
    float* __restrict__ out)
{
    extern __shared__ __align__(16) char smem[];
    uint2* Wq = (uint2*)(smem + SM_W);
    uint2* Xq = (uint2*)(smem + SM_X);
    char*  Xq8 = (char*)(smem + SM_X);
    float* sbs = (float*)(smem + SM_SB);
    float* bias_s = (float*)(smem + SM_BIAS);
    float* srowb = (float*)(smem + SM_SROW);    // [2][64]
    float* invs = (float*)(smem + SM_INV);
    float* rmp  = (float*)(smem + SM_RMP);
    float* Un   = (float*)(smem + SM_UNB);
    float* Fs   = (float*)smem;                  // alias, post-GEMM
    float* ows  = (float*)(smem + SM_OWS);

    const int tid = threadIdx.x;
    const int lane = tid & 31;
    const int wid = tid >> 5;
    const int wm = wid >> 2, wn = wid & 3;
    const int lq = lane & 3, lr = lane >> 2;
    const int tokBase = blockIdx.x * 64;

    for (int i = tid; i < 768; i += 256) sbs[i] = sbg[i];
    for (int i = tid; i < 640; i += 256) {
        int slot = i >> 7, c = i & 127;
        float v;
        if (slot == 0)      v = ba[c] + bi[c];
        else if (slot == 1) v = b1[c];
        else if (slot == 2) v = b2[c];
        else if (slot == 3) v = b1[128 + c];
        else                v = b2[128 + c];
        bias_s[i] = v;
    }

    int P1[2][4][4], P23[2][4][4];
    float xres[2][4][4];

    // ---- layer 1a: quant(relu(act)) @ Wq0 ----
    stageX_quant(Xq, act, tokBase, tid, srowb);          // srow buf0
    copyW(Wq, 0, tid);
    __syncthreads();
    zeroP(P1, P23);
    gemm(Wq, Xq, P1, P23, wm, wn, lane);
    __syncthreads();
    {
        const float* srp = srowb;
        const float* sbl = sbs;
#pragma unroll
        for (int mt = 0; mt < 2; mt++)
#pragma unroll
            for (int nt = 0; nt < 4; nt++) {
                int r0 = wm * 32 + mt * 16 + lr;
                int c0 = wn * 32 + nt * 8 + lq * 2;
                xres[mt][nt][0] = DEQ_VAL(mt, nt, 0, r0, c0);
                xres[mt][nt][1] = DEQ_VAL(mt, nt, 1, r0, c0 + 1);
                xres[mt][nt][2] = DEQ_VAL(mt, nt, 2, r0 + 8, c0);
                xres[mt][nt][3] = DEQ_VAL(mt, nt, 3, r0 + 8, c0 + 1);
            }
    }
    // ---- layer 1b: += quant(relu(init)) @ Wq1 ----
    stageX_quant(Xq, init_act, tokBase, tid, srowb + 64);  // srow buf1
    copyW(Wq, 1, tid);
    __syncthreads();
    zeroP(P1, P23);
    gemm(Wq, Xq, P1, P23, wm, wn, lane);
    __syncthreads();
    {
        const float* srp = srowb + 64;
        const float* sbl = sbs + 128;
#pragma unroll
        for (int mt = 0; mt < 2; mt++)
#pragma unroll
            for (int nt = 0; nt < 4; nt++) {
                int r0 = wm * 32 + mt * 16 + lr;
                int c0 = wn * 32 + nt * 8 + lq * 2;
                float bv0 = bias_s[c0], bv1 = bias_s[c0 + 1];
                xres[mt][nt][0] += DEQ_VAL(mt, nt, 0, r0, c0) + bv0;
                xres[mt][nt][1] += DEQ_VAL(mt, nt, 1, r0, c0 + 1) + bv1;
                xres[mt][nt][2] += DEQ_VAL(mt, nt, 2, r0 + 8, c0) + bv0;
                xres[mt][nt][3] += DEQ_VAL(mt, nt, 3, r0 + 8, c0 + 1) + bv1;
            }
    }
    {
        float vr[2][4][4];
#pragma unroll
        for (int mt = 0; mt < 2; mt++)
#pragma unroll
            for (int nt = 0; nt < 4; nt++)
#pragma unroll
                for (int d = 0; d < 4; d++) vr[mt][nt][d] = fmaxf(xres[mt][nt][d], 0.f);
        quant_epi(vr, Xq8, rmp, srowb, invs, wm, wn, lq, lr, tid);   // -> buf0
    }

    // ---- resnet blocks ----
#pragma unroll 1
    for (int blk = 0; blk < 2; blk++) {
        // w1: h = relu(x@w1 + b1)
        copyW(Wq, 2 + blk * 2, tid);
        __syncthreads();
        zeroP(P1, P23);
        gemm(Wq, Xq, P1, P23, wm, wn, lane);
        __syncthreads();
        {
            const float* srp = srowb;                         // buf0 (x)
            const float* sbl = sbs + 128 * (2 + blk * 2);
            const float* bb = bias_s + 128 * (1 + blk * 2);
            float hv[2][4][4];
#pragma unroll
            for (int mt = 0; mt < 2; mt++)
#pragma unroll
                for (int nt = 0; nt < 4; nt++) {
                    int r0 = wm * 32 + mt * 16 + lr;
                    int c0 = wn * 32 + nt * 8 + lq * 2;
                    float bv0 = bb[c0], bv1 = bb[c0 + 1];
                    hv[mt][nt][0] = fmaxf(DEQ_VAL(mt, nt, 0, r0, c0) + bv0, 0.f);
                    hv[mt][nt][1] = fmaxf(DEQ_VAL(mt, nt, 1, r0, c0 + 1) + bv1, 0.f);
                    hv[mt][nt][2] = fmaxf(DEQ_VAL(mt, nt, 2, r0 + 8, c0) + bv0, 0.f);
                    hv[mt][nt][3] = fmaxf(DEQ_VAL(mt, nt, 3, r0 + 8, c0 + 1) + bv1, 0.f);
                }
            quant_epi(hv, Xq8, rmp, srowb + 64, invs, wm, wn, lq, lr, tid);  // -> buf1
        }
        // w2: x += h@w2 + b2
        copyW(Wq, 3 + blk * 2, tid);
        __syncthreads();
        zeroP(P1, P23);
        gemm(Wq, Xq, P1, P23, wm, wn, lane);
        __syncthreads();
        {
            const float* srp = srowb + 64;                    // buf1 (h)
            const float* sbl = sbs + 128 * (3 + blk * 2);
            const float* bb = bias_s + 128 * (2 + blk * 2);
#pragma unroll
            for (int mt = 0; mt < 2; mt++)
#pragma unroll
                for (int nt = 0; nt < 4; nt++) {
                    int r0 = wm * 32 + mt * 16 + lr;
                    int c0 = wn * 32 + nt * 8 + lq * 2;
                    float bv0 = bb[c0], bv1 = bb[c0 + 1];
                    xres[mt][nt][0] += DEQ_VAL(mt, nt, 0, r0, c0) + bv0;
                    xres[mt][nt][1] += DEQ_VAL(mt, nt, 1, r0, c0 + 1) + bv1;
                    xres[mt][nt][2] += DEQ_VAL(mt, nt, 2, r0 + 8, c0) + bv0;
                    xres[mt][nt][3] += DEQ_VAL(mt, nt, 3, r0 + 8, c0 + 1) + bv1;
                }
        }
        if (blk == 0) {
            float vr[2][4][4];
#pragma unroll
            for (int mt = 0; mt < 2; mt++)
#pragma unroll
                for (int nt = 0; nt < 4; nt++)
#pragma unroll
                    for (int d = 0; d < 4; d++) vr[mt][nt][d] = fmaxf(xres[mt][nt][d], 0.f);
            quant_epi(vr, Xq8, rmp, srowb, invs, wm, wn, lq, lr, tid);       // -> buf0
        } else {
#pragma unroll
            for (int mt = 0; mt < 2; mt++)
#pragma unroll
                for (int nt = 0; nt < 4; nt++) {
                    int r0 = wm * 32 + mt * 16 + lr;
                    int c0 = wn * 32 + nt * 8 + lq * 2;
                    Fs[r0 * FS_STRIDE + c0]           = fmaxf(xres[mt][nt][0], 0.f);
                    Fs[r0 * FS_STRIDE + c0 + 1]       = fmaxf(xres[mt][nt][1], 0.f);
                    Fs[(r0 + 8) * FS_STRIDE + c0]     = fmaxf(xres[mt][nt][2], 0.f);
                    Fs[(r0 + 8) * FS_STRIDE + c0 + 1] = fmaxf(xres[mt][nt][3], 0.f);
                }
        }
    }
    for (int i = tid; i < 1792; i += 256) ows[i] = ow[i];
    __syncthreads();

    // ---- head: unnorm = relu(x) @ ow + ob ----
    {
        int t = tid & 63, hh = tid >> 6;
        int ch0 = hh * 4;
        int cnt = (hh == 3) ? 2 : 4;
        float a0 = 0.f, a1 = 0.f, a2 = 0.f, a3 = 0.f;
        const float* Xp = Fs + t * FS_STRIDE;
#pragma unroll 4
        for (int k = 0; k < 128; k++) {
            float xv = Xp[k];
            const float* wp = ows + k * 14 + ch0;
            a0 += xv * wp[0];
            a1 += xv * wp[1];
            if (hh != 3) { a2 += xv * wp[2]; a3 += xv * wp[3]; }
        }
        Un[t * 14 + ch0 + 0] = a0 + ob[ch0 + 0];
        Un[t * 14 + ch0 + 1] = a1 + ob[ch0 + 1];
        if (cnt == 4) {
            Un[t * 14 + ch0 + 2] = a2 + ob[ch0 + 2];
            Un[t * 14 + ch0 + 3] = a3 + ob[ch0 + 3];
        }
    }
    __syncthreads();

    for (int i = tid; i < 448; i += 256) {
        int t = i & 63, a = i >> 6;
        float sv = Un[t * 14 + 2 * a];
        float cv = Un[t * 14 + 2 * a + 1];
        float inv = rsqrtf(sv * sv + cv * cv + 1e-12f);
        int tok = tokBase + t;
        out[OUT_UN + tok * 14 + 2 * a]      = sv;
        out[OUT_UN + tok * 14 + 2 * a + 1]  = cv;
        out[OUT_ANG + tok * 14 + 2 * a]     = sv * inv;
        out[OUT_ANG + tok * 14 + 2 * a + 1] = cv * inv;
    }
}

// ---------------------------------------------------------------------------
// Kernel B: frames + atoms (unchanged from R9)
// ---------------------------------------------------------------------------

__device__ __forceinline__ void compose34(float* __restrict__ o,
                                          const float* __restrict__ A,
                                          const float* __restrict__ Bm) {
#pragma unroll
    for (int r = 0; r < 3; r++) {
        float a0 = A[r*4+0], a1 = A[r*4+1], a2 = A[r*4+2], a3 = A[r*4+3];
#pragma unroll
        for (int c = 0; c < 3; c++)
            o[r*4+c] = a0 * Bm[c] + a1 * Bm[4+c] + a2 * Bm[8+c];
        o[r*4+3] = a0 * Bm[3] + a1 * Bm[7] + a2 * Bm[11] + a3;
    }
}

__global__ void __launch_bounds__(256) frames_kernel(
    const int* __restrict__ seq, const float* __restrict__ backb,
    const float* __restrict__ dframes, const int* __restrict__ gidx,
    const float* __restrict__ amask, const float* __restrict__ lit,
    float* __restrict__ out)
{
    __shared__ float sdf[21 * 8 * 16];
    __shared__ float slit[21 * 14 * 3];
    __shared__ float sam[21 * 14];
    __shared__ int   sgi[21 * 14];
    __shared__ float saf[32][8][12];

    const int tid = threadIdx.x;
    for (int i = tid; i < 2688; i += 256) sdf[i] = dframes[i];
    for (int i = tid; i < 882; i += 256) slit[i] = lit[i];
    for (int i = tid; i < 294; i += 256) { sam[i] = amask[i]; sgi[i] = gidx[i]; }
    __syncthreads();

    const int g = tid & 7;
    const int tl = tid >> 3;

#pragma unroll 1
    for (int it = 0; it < 4; it++) {
        const int tok = blockIdx.x * 128 + it * 32 + tl;
        const int s = seq[tok];

        float sv, cv;
        if (g == 0) { sv = 0.f; cv = 1.f; }
        else {
            sv = out[OUT_ANG + tok * 14 + (g - 1) * 2];
            cv = out[OUT_ANG + tok * 14 + (g - 1) * 2 + 1];
        }

        const float* df = sdf + (s * 8 + g) * 16;
        float F[12];
#pragma unroll
        for (int r = 0; r < 3; r++) {
            float m0 = df[r*4+0], m1 = df[r*4+1], m2 = df[r*4+2], m3 = df[r*4+3];
            F[r*4+0] = m0;
            F[r*4+1] = cv * m1 + sv * m2;
            F[r*4+2] = cv * m2 - sv * m1;
            F[r*4+3] = m3;
        }
#pragma unroll
        for (int i = 0; i < 12; i++) saf[tl][g][i] = F[i];
        __syncthreads();

        if (g == 0) {
            float A[12], Bm[12], Cm[12];
#pragma unroll
            for (int i = 0; i < 12; i++) A[i] = saf[tl][4][i];
#pragma unroll
            for (int i = 0; i < 12; i++) Bm[i] = saf[tl][5][i];
            compose34(Cm, A, Bm);
#pragma unroll
            for (int i = 0; i < 12; i++) saf[tl][5][i] = Cm[i];
#pragma unroll
            for (int i = 0; i < 12; i++) Bm[i] = saf[tl][6][i];
            compose34(A, Cm, Bm);
#pragma unroll
            for (int i = 0; i < 12; i++) saf[tl][6][i] = A[i];
#pragma unroll
            for (int i = 0; i < 12; i++) Bm[i] = saf[tl][7][i];
            compose34(Cm, A, Bm);
#pragma unroll
            for (int i = 0; i < 12; i++) saf[tl][7][i] = Cm[i];
        }
        __syncthreads();

        {
            const float4* bk4 = (const float4*)(backb + (size_t)tok * 16);
            float Bk[12], L[12], G[12];
            float4 b0 = bk4[0], b1v = bk4[1], b2v = bk4[2];
            Bk[0]=b0.x; Bk[1]=b0.y; Bk[2]=b0.z;  Bk[3]=b0.w;
            Bk[4]=b1v.x; Bk[5]=b1v.y; Bk[6]=b1v.z; Bk[7]=b1v.w;
            Bk[8]=b2v.x; Bk[9]=b2v.y; Bk[10]=b2v.z; Bk[11]=b2v.w;
#pragma unroll
            for (int i = 0; i < 12; i++) L[i] = saf[tl][g][i];
            compose34(G, Bk, L);
            float* o = out + OUT_ATG + (size_t)tok * 128 + g * 16;
            ((float4*)o)[0] = make_float4(G[0], G[1], G[2], G[3]);
            ((float4*)o)[1] = make_float4(G[4], G[5], G[6], G[7]);
            ((float4*)o)[2] = make_float4(G[8], G[9], G[10], G[11]);
            ((float4*)o)[3] = make_float4(0.f, 0.f, 0.f, 1.f);
#pragma unroll
            for (int i = 0; i < 12; i++) saf[tl][g][i] = G[i];
        }
        __syncthreads();

        for (int i = tid; i < 448; i += 256) {
            int t2 = i / 14;
            int a = i % 14;
            int tok2 = blockIdx.x * 128 + it * 32 + t2;
            int s2 = seq[tok2];
            int idx = s2 * 14 + a;
            int gg = sgi[idx];
            float m = sam[idx];
            float lx = slit[idx*3+0], ly = slit[idx*3+1], lz = slit[idx*3+2];
            const float* Fp = saf[t2][gg];
            float px = (Fp[0]*lx + Fp[1]*ly + Fp[2]*lz  + Fp[3])  * m;
            float py = (Fp[4]*lx + Fp[5]*ly + Fp[6]*lz  + Fp[7])  * m;
            float pz = (Fp[8]*lx + Fp[9]*ly + Fp[10]*lz + Fp[11]) * m;
            float* po = out + OUT_POS + (size_t)tok2 * 42 + a * 3;
            po[0] = px; po[1] = py; po[2] = pz;
        }
        __syncthreads();
    }
}

// ---------------------------------------------------------------------------

extern "C" void kernel_launch(void* const* d_in, const int* in_sizes, int n_in,
                              void* d_out, int out_size) {
    const int*   seq      = (const int*)  d_in[0];
    const float* backb    = (const float*)d_in[1];
    const float* act      = (const float*)d_in[2];
    const float* init_act = (const float*)d_in[3];
    const float* Wa       = (const float*)d_in[4];
    const float* ba       = (const float*)d_in[5];
    const float* Wi       = (const float*)d_in[6];
    const float* bi       = (const float*)d_in[7];
    const float* w1       = (const float*)d_in[8];
    const float* b1       = (const float*)d_in[9];
    const float* w2       = (const float*)d_in[10];
    const float* b2       = (const float*)d_in[11];
    const float* ow       = (const float*)d_in[12];
    const float* ob       = (const float*)d_in[13];
    const float* dframes  = (const float*)d_in[14];
    const int*   gidx     = (const int*)  d_in[15];
    const float* amask    = (const float*)d_in[16];
    const float* lit      = (const float*)d_in[17];
    float* out = (float*)d_out;

    cudaFuncSetAttribute(mlp_kernel, cudaFuncAttributeMaxDynamicSharedMemorySize, SM_TOT);

    prep1<<<6, 128>>>(Wa, Wi, w1, w2);
    prep2<<<768, 32>>>(Wa, Wi, w1, w2);
    mlp_kernel<<<NTOK / 64, 256, SM_TOT>>>(act, init_act, ba, bi, b1, b2, ow, ob, out);
    frames_kernel<<<NTOK / 128, 256>>>(seq, backb, dframes, gidx, amask, lit, out);
}